// round 13
// baseline (speedup 1.0000x reference)
#include <cuda_runtime.h>
#include <cuda_bf16.h>
#include <cuda_fp16.h>
#include <cstdint>

// ===========================================================================
// AxisAttention: bf16x3 (m16n8k16) for q/k proj + QK^T; fp16 for P@(VW);
// out-projection folded algebraically: Wvo = Wv@Wo, bvo = bv@Wo + bo,
// out = P @ (kv@Wvo) + bvo + query. B=4, N=2048, D=DA=512.
// ===========================================================================

constexpr int BB  = 4;
constexpr int SEQ = 2048;
constexpr int DIM = 512;
constexpr float SCALE_F = 22.62741699796952f;

constexpr size_t BND = (size_t)BB * SEQ * DIM;

// ---------------- device global scratch -------------------------------------
__device__ __nv_bfloat16 g_in_bh[2 * BND];
__device__ __nv_bfloat16 g_in_bl[2 * BND];
__device__ float         g_kv_t32[BND];
__device__ __nv_bfloat16 g_qk_bh[2 * BND];
__device__ __nv_bfloat16 g_qk_bl[2 * BND];
__device__ __half g_vwt[(size_t)BB * DIM * SEQ];     // (kv@Wvo)^T fp16
__device__ float  g_s[(size_t)BB * SEQ * SEQ];
__device__ __half g_pf[(size_t)BB * SEQ * SEQ];
__device__ __nv_bfloat16 g_wqk_bh[2 * DIM * DIM];
__device__ __nv_bfloat16 g_wqk_bl[2 * DIM * DIM];
__device__ float g_wvnt[DIM * DIM];   // Wv non-transposed, perm cols
__device__ float g_wot[DIM * DIM];    // Wo^T, perm cols
__device__ float g_wvot[DIM * DIM];   // (Wv@Wo)^T, perm cols
__device__ float g_bvo[DIM];          // bv@Wo + bo

// ---------------- helpers ----------------------------------------------------
__device__ __forceinline__ uint32_t smem_u32(const void* p) {
    uint32_t a;
    asm("{ .reg .u64 t; cvta.to.shared.u64 t, %1; cvt.u32.u64 %0, t; }"
        : "=r"(a) : "l"(p));
    return a;
}
__device__ __forceinline__ float tf32_rna(float x) {
    uint32_t u;
    asm("cvt.rna.tf32.f32 %0, %1;" : "=r"(u) : "f"(x));
    return __uint_as_float(u);
}
__device__ __forceinline__ void cp16(uint32_t saddr, const void* g) {
    asm volatile("cp.async.cg.shared.global [%0], [%1], 16;"
                 :: "r"(saddr), "l"(g) : "memory");
}
__device__ __forceinline__ void cp_commit() {
    asm volatile("cp.async.commit_group;" ::: "memory");
}
template <int N>
__device__ __forceinline__ void cp_wait() {
    asm volatile("cp.async.wait_group %0;" :: "n"(N) : "memory");
}

__device__ __forceinline__ int permk(int k) {
    const int lo = k & 7;
    return (k & ~15) | ((k & 8) + 2 * (lo & 3) + (lo >> 2));
}
__device__ __forceinline__ int permkb(int k) {
    const int t = k & 15;
    const int q = (t & 7) >> 1, d = t & 1, e = t >> 3;
    return (k & ~15) | (4 * q + 2 * e + d);
}

__device__ __forceinline__ void mma8(float* c, float a0, float a1, float a2,
                                     float a3, float b0, float b1) {
    asm volatile(
        "mma.sync.aligned.m16n8k8.row.col.f32.tf32.tf32.f32 "
        "{%0,%1,%2,%3}, {%4,%5,%6,%7}, {%8,%9}, {%0,%1,%2,%3};"
        : "+f"(c[0]), "+f"(c[1]), "+f"(c[2]), "+f"(c[3])
        : "r"(__float_as_uint(a0)), "r"(__float_as_uint(a1)),
          "r"(__float_as_uint(a2)), "r"(__float_as_uint(a3)),
          "r"(__float_as_uint(b0)), "r"(__float_as_uint(b1)));
}
__device__ __forceinline__ void mma16(float* c, uint32_t a0, uint32_t a1,
                                      uint32_t a2, uint32_t a3,
                                      uint32_t b0, uint32_t b1) {
    asm volatile(
        "mma.sync.aligned.m16n8k16.row.col.f32.bf16.bf16.f32 "
        "{%0,%1,%2,%3}, {%4,%5,%6,%7}, {%8,%9}, {%0,%1,%2,%3};"
        : "+f"(c[0]), "+f"(c[1]), "+f"(c[2]), "+f"(c[3])
        : "r"(a0), "r"(a1), "r"(a2), "r"(a3), "r"(b0), "r"(b1));
}
__device__ __forceinline__ void mma16h(float* c, uint32_t a0, uint32_t a1,
                                       uint32_t a2, uint32_t a3,
                                       uint32_t b0, uint32_t b1) {
    asm volatile(
        "mma.sync.aligned.m16n8k16.row.col.f32.f16.f16.f32 "
        "{%0,%1,%2,%3}, {%4,%5,%6,%7}, {%8,%9}, {%0,%1,%2,%3};"
        : "+f"(c[0]), "+f"(c[1]), "+f"(c[2]), "+f"(c[3])
        : "r"(a0), "r"(a1), "r"(a2), "r"(a3), "r"(b0), "r"(b1));
}
__device__ __forceinline__ uint32_t f2u(float x) { return __float_as_uint(x); }

// ===========================================================================
// bf16 split GEMM (hh+hl+lh): CTA 128x128, 256 thr occ 2, warp 64x32 (IT=4),
// K-chunk 32. EPI 0: bf16 hi/lo split + bias (staged); EPI 2: alpha fp32
// (permkb cols, staged).
// ===========================================================================
template <int EPI>
__global__ void __launch_bounds__(256, 2) gemm_bf16(
    const __nv_bfloat16* __restrict__ Ahi, const __nv_bfloat16* __restrict__ Alo,
    const __nv_bfloat16* __restrict__ Bhi, const __nv_bfloat16* __restrict__ Blo,
    void* __restrict__ Cp, void* __restrict__ C2p,
    const float* __restrict__ bias, const float* __restrict__ bias2,
    int K, int lda, int ldb, int ldc,
    size_t sA, size_t sB, size_t sC, float alpha)
{
    constexpr int IT = 4, WN = 4;
    constexpr int ROWB  = 160;
    constexpr int TILEB = 128 * ROWB;
    constexpr int STAGEB = 2 * TILEB;

    extern __shared__ char smc[];
    const uint32_t sb = smem_u32(smc);

    const int tid    = threadIdx.x;
    const int lane   = tid & 31;
    const int wid    = tid >> 5;
    const int warp_m = wid >> 2;
    const int warp_n = wid & 3;
    const int q      = lane & 3;
    const int n0 = blockIdx.x * 128;
    const int m0 = blockIdx.y * 128;
    const int z  = blockIdx.z;

    const float* bias_z = (EPI == 0 && z == 1) ? bias2 : bias;

    const __nv_bfloat16* A0 = Ahi + (size_t)z * sA + (size_t)m0 * lda;
    const __nv_bfloat16* A1 = Alo + (size_t)z * sA + (size_t)m0 * lda;
    const __nv_bfloat16* B0 = Bhi + (size_t)z * sB + (size_t)n0 * ldb;
    const __nv_bfloat16* B1 = Blo + (size_t)z * sB + (size_t)n0 * ldb;

    float acc[IT][WN][4];
#pragma unroll
    for (int i = 0; i < IT; i++)
#pragma unroll
        for (int j = 0; j < WN; j++)
#pragma unroll
            for (int l = 0; l < 4; l++) acc[i][j][l] = 0.0f;

    const int nch = K / 32;

    auto load_stage = [&](int buf, int c) {
        const uint32_t st = sb + (uint32_t)buf * STAGEB;
#pragma unroll
        for (int i = 0; i < 8; i++) {
            const int idx = tid + i * 256;
            const int tile = idx >> 10;
            const int w    = idx & 1023;
            const int row  = w >> 3;
            const int h    = (w >> 2) & 1;
            const int cc   = w & 3;
            const __nv_bfloat16* src =
                tile ? (h ? B1 : B0) : (h ? A1 : A0);
            const int ld = tile ? ldb : lda;
            cp16(st + (uint32_t)(tile * TILEB + row * ROWB + h * 64 + cc * 16),
                 src + (size_t)row * ld + c * 32 + cc * 8);
        }
    };

    load_stage(0, 0);
    cp_commit();

    const int arow0 = warp_m * 64 + (lane >> 2);
    const int bcol0 = warp_n * 32 + (lane >> 2);

    for (int c = 0; c < nch; c++) {
        if (c + 1 < nch) {
            load_stage((c + 1) & 1, c + 1);
            cp_commit();
            cp_wait<1>();
        } else {
            cp_wait<0>();
        }
        __syncthreads();

        const char* stg = smc + (size_t)(c & 1) * STAGEB;
        const char* Ab  = stg;
        const char* Bb  = stg + TILEB;

#pragma unroll
        for (int b = 0; b < 2; b++) {
            const int kb = b * 32 + 8 * q;
            float2 Ah0[IT], Ah1[IT];
#pragma unroll
            for (int i = 0; i < IT; i++) {
                const int row = arow0 + i * 16;
                Ah0[i] = *reinterpret_cast<const float2*>(Ab + row * ROWB + kb);
                Ah1[i] = *reinterpret_cast<const float2*>(Ab + (row + 8) * ROWB + kb);
            }
            float2 Bh[WN];
#pragma unroll
            for (int j = 0; j < WN; j++)
                Bh[j] = *reinterpret_cast<const float2*>(
                    Bb + (bcol0 + j * 8) * ROWB + kb);
#pragma unroll
            for (int i = 0; i < IT; i++)
#pragma unroll
                for (int j = 0; j < WN; j++)
                    mma16(acc[i][j], f2u(Ah0[i].x), f2u(Ah1[i].x),
                          f2u(Ah0[i].y), f2u(Ah1[i].y), f2u(Bh[j].x), f2u(Bh[j].y));
            float2 Bl[WN];
#pragma unroll
            for (int j = 0; j < WN; j++)
                Bl[j] = *reinterpret_cast<const float2*>(
                    Bb + (bcol0 + j * 8) * ROWB + 64 + kb);
#pragma unroll
            for (int i = 0; i < IT; i++)
#pragma unroll
                for (int j = 0; j < WN; j++)
                    mma16(acc[i][j], f2u(Ah0[i].x), f2u(Ah1[i].x),
                          f2u(Ah0[i].y), f2u(Ah1[i].y), f2u(Bl[j].x), f2u(Bl[j].y));
            float2 Al0[IT], Al1[IT];
#pragma unroll
            for (int i = 0; i < IT; i++) {
                const int row = arow0 + i * 16;
                Al0[i] = *reinterpret_cast<const float2*>(Ab + row * ROWB + 64 + kb);
                Al1[i] = *reinterpret_cast<const float2*>(Ab + (row + 8) * ROWB + 64 + kb);
            }
#pragma unroll
            for (int i = 0; i < IT; i++)
#pragma unroll
                for (int j = 0; j < WN; j++)
                    mma16(acc[i][j], f2u(Al0[i].x), f2u(Al1[i].x),
                          f2u(Al0[i].y), f2u(Al1[i].y), f2u(Bh[j].x), f2u(Bh[j].y));
        }
        __syncthreads();
    }

    // ---------------- staged epilogues ----------------
    if (EPI == 0) {
        __nv_bfloat16* sh = reinterpret_cast<__nv_bfloat16*>(smc);
        __nv_bfloat16* sl = sh + 128 * 128;
#pragma unroll
        for (int i = 0; i < IT; i++) {
#pragma unroll
            for (int j = 0; j < WN; j++) {
                const float* a4 = acc[i][j];
                const int lr = warp_m * 64 + i * 16 + (lane >> 2);
                const int lc = warp_n * 32 + j * 8 + 2 * q;
                const float bx = bias_z[n0 + lc], by = bias_z[n0 + lc + 1];
                const int p0 = permkb(lc), p1 = permkb(lc + 1);
                const float v[4] = {a4[0] + bx, a4[1] + by, a4[2] + bx, a4[3] + by};
                const int rr[4] = {lr, lr, lr + 8, lr + 8};
                const int pp[4] = {p0, p1, p0, p1};
#pragma unroll
                for (int u = 0; u < 4; u++) {
                    const __nv_bfloat16 h = __float2bfloat16(v[u]);
                    sh[rr[u] * 128 + pp[u]] = h;
                    sl[rr[u] * 128 + pp[u]] =
                        __float2bfloat16(v[u] - __bfloat162float(h));
                }
            }
        }
        __syncthreads();
        __nv_bfloat16* Cz  = (__nv_bfloat16*)Cp  + (size_t)z * sC;
        __nv_bfloat16* C2z = (__nv_bfloat16*)C2p + (size_t)z * sC;
#pragma unroll
        for (int t = 0; t < 8; t++) {
            const int idx = tid + t * 256;
            const int row = idx >> 4;
            const int c16 = idx & 15;
            *reinterpret_cast<uint4*>(Cz + (size_t)(m0 + row) * ldc + n0 + c16 * 8) =
                *reinterpret_cast<const uint4*>(sh + row * 128 + c16 * 8);
            *reinterpret_cast<uint4*>(C2z + (size_t)(m0 + row) * ldc + n0 + c16 * 8) =
                *reinterpret_cast<const uint4*>(sl + row * 128 + c16 * 8);
        }
    } else {
        float* ss = reinterpret_cast<float*>(smc);
#pragma unroll
        for (int i = 0; i < IT; i++) {
#pragma unroll
            for (int j = 0; j < WN; j++) {
                const float* a4 = acc[i][j];
                const int lr = warp_m * 64 + i * 16 + (lane >> 2);
                const int lc = warp_n * 32 + j * 8 + 2 * q;
                const int p0 = permkb(lc), p1 = permkb(lc + 1);
                ss[lr * 128 + p0]       = alpha * a4[0];
                ss[lr * 128 + p1]       = alpha * a4[1];
                ss[(lr + 8) * 128 + p0] = alpha * a4[2];
                ss[(lr + 8) * 128 + p1] = alpha * a4[3];
            }
        }
        __syncthreads();
        float* Cz = (float*)Cp + (size_t)z * sC;
#pragma unroll
        for (int t = 0; t < 16; t++) {
            const int idx = tid + t * 256;
            const int row = idx >> 5;
            const int c8  = idx & 31;
            *reinterpret_cast<uint4*>(Cz + (size_t)(m0 + row) * ldc + n0 + c8 * 4) =
                *reinterpret_cast<const uint4*>(ss + row * 128 + c8 * 4);
        }
    }
}

// ===========================================================================
// fp16 single-pass GEMM (final): out = P @ VW + bvo[n] + query[m,n].
// CTA 128x128, 256 thr occ 2, warp 64x32, K-chunk 32, ROWB=80.
// ===========================================================================
__global__ void __launch_bounds__(256, 2) gemm_f16(
    const __half* __restrict__ A, const __half* __restrict__ B,
    float* __restrict__ C,
    const float* __restrict__ bias, const float* __restrict__ resid,
    int K, int lda, int ldb, int ldc,
    size_t sA, size_t sB, size_t sC)
{
    constexpr int IT = 4;
    constexpr int ROWB  = 80;
    constexpr int TILEB = 128 * ROWB;
    constexpr int STAGEB = 2 * TILEB;

    extern __shared__ char smc[];
    const uint32_t sb = smem_u32(smc);

    const int tid    = threadIdx.x;
    const int lane   = tid & 31;
    const int wid    = tid >> 5;
    const int warp_m = wid >> 2;
    const int warp_n = wid & 3;
    const int q      = lane & 3;
    const int n0 = blockIdx.x * 128;
    const int m0 = blockIdx.y * 128;
    const int z  = blockIdx.z;

    const __half* A0 = A + (size_t)z * sA + (size_t)m0 * lda;
    const __half* B0 = B + (size_t)z * sB + (size_t)n0 * ldb;

    float acc[IT][4][4];
#pragma unroll
    for (int i = 0; i < IT; i++)
#pragma unroll
        for (int j = 0; j < 4; j++)
#pragma unroll
            for (int l = 0; l < 4; l++) acc[i][j][l] = 0.0f;

    const int nch = K / 32;

    auto load_stage = [&](int buf, int c) {
        const uint32_t st = sb + (uint32_t)buf * STAGEB;
#pragma unroll
        for (int i = 0; i < 4; i++) {
            const int idx = tid + i * 256;
            const int tile = idx >> 9;
            const int w    = idx & 511;
            const int row  = w >> 2;
            const int cc   = w & 3;
            const __half* src = tile ? B0 : A0;
            const int ld = tile ? ldb : lda;
            cp16(st + (uint32_t)(tile * TILEB + row * ROWB + cc * 16),
                 src + (size_t)row * ld + c * 32 + cc * 8);
        }
    };

    load_stage(0, 0);
    cp_commit();

    const int arow0 = warp_m * 64 + (lane >> 2);
    const int bcol0 = warp_n * 32 + (lane >> 2);

    for (int c = 0; c < nch; c++) {
        if (c + 1 < nch) {
            load_stage((c + 1) & 1, c + 1);
            cp_commit();
            cp_wait<1>();
        } else {
            cp_wait<0>();
        }
        __syncthreads();

        const char* stg = smc + (size_t)(c & 1) * STAGEB;
        const char* Ab  = stg;
        const char* Bb  = stg + TILEB;

#pragma unroll
        for (int b = 0; b < 2; b++) {
            const int kb = b * 32 + 8 * q;
            float2 a0[IT], a1[IT], b0[4];
#pragma unroll
            for (int i = 0; i < IT; i++) {
                const int row = arow0 + i * 16;
                a0[i] = *reinterpret_cast<const float2*>(Ab + row * ROWB + kb);
                a1[i] = *reinterpret_cast<const float2*>(Ab + (row + 8) * ROWB + kb);
            }
#pragma unroll
            for (int j = 0; j < 4; j++)
                b0[j] = *reinterpret_cast<const float2*>(
                    Bb + (bcol0 + j * 8) * ROWB + kb);
#pragma unroll
            for (int i = 0; i < IT; i++)
#pragma unroll
                for (int j = 0; j < 4; j++)
                    mma16h(acc[i][j], f2u(a0[i].x), f2u(a1[i].x),
                           f2u(a0[i].y), f2u(a1[i].y), f2u(b0[j].x), f2u(b0[j].y));
        }
        __syncthreads();
    }

    // final epilogue: + bvo[n] + query residual, natural layout
    float* Cz = C + (size_t)z * sC;
    const float* Rz = resid + (size_t)z * sC;
#pragma unroll
    for (int i = 0; i < IT; i++) {
#pragma unroll
        for (int j = 0; j < 4; j++) {
            const float* a4 = acc[i][j];
            const int r0 = m0 + warp_m * 64 + i * 16 + (lane >> 2);
            const int c0 = n0 + warp_n * 32 + j * 8 + 2 * q;
            const float bx = bias[c0], by = bias[c0 + 1];
            const float2 rs0 = *reinterpret_cast<const float2*>(
                &Rz[(size_t)r0 * ldc + c0]);
            const float2 rs1 = *reinterpret_cast<const float2*>(
                &Rz[(size_t)(r0 + 8) * ldc + c0]);
            float2 v0, v1;
            v0.x = a4[0] + bx + rs0.x; v0.y = a4[1] + by + rs0.y;
            v1.x = a4[2] + bx + rs1.x; v1.y = a4[3] + by + rs1.y;
            *reinterpret_cast<float2*>(&Cz[(size_t)r0 * ldc + c0]) = v0;
            *reinterpret_cast<float2*>(&Cz[(size_t)(r0 + 8) * ldc + c0]) = v1;
        }
    }
}

// ===========================================================================
// tf32 1-pass GEMM: CTA 128x128, 256 thr occ 2, warp 64x32, K-chunk 32.
// EPI 1: transposed fp16 output + optional bias (permkb seq)  [VW^T]
// EPI 5: transposed fp32 output, permk on m                   [Wvo^T]
// ===========================================================================
constexpr int LDW    = 40;
constexpr int TILE_F = 128 * LDW;
constexpr int TILE_B = TILE_F * 4;

__device__ __forceinline__ void load_tile32(
    uint32_t sbase, const float* __restrict__ g, int ld, int tid)
{
#pragma unroll
    for (int i = 0; i < 4; i++) {
        const int f  = tid + i * 256;
        const int r  = f >> 3;
        const int c4 = (f & 7) << 2;
        cp16(sbase + (uint32_t)(r * LDW + c4) * 4, g + (size_t)r * ld + c4);
    }
}

template <int EPI>
__global__ void __launch_bounds__(256, 2) gemm_t32(
    const float* __restrict__ A, const float* __restrict__ B,
    float* __restrict__ C,
    const float* __restrict__ bias,
    int K, int lda, int ldb,
    size_t sA, size_t sB)
{
    constexpr int IT = 4;
    extern __shared__ float smf[];
    const uint32_t sb = smem_u32(smf);

    const int tid    = threadIdx.x;
    const int lane   = tid & 31;
    const int wid    = tid >> 5;
    const int warp_m = wid >> 2;
    const int warp_n = wid & 3;
    const int n0 = blockIdx.x * 128;
    const int m0 = blockIdx.y * 128;
    const int z  = blockIdx.z;

    const float* A0 = A + (size_t)z * sA + (size_t)m0 * lda;
    const float* B0 = B + (size_t)z * sB + (size_t)n0 * ldb;

    float acc[IT][4][4];
#pragma unroll
    for (int i = 0; i < IT; i++)
#pragma unroll
        for (int j = 0; j < 4; j++)
#pragma unroll
            for (int l = 0; l < 4; l++) acc[i][j][l] = 0.0f;

    const int nch = K / 32;

    auto load_stage = [&](int buf, int c) {
        const uint32_t st = sb + (uint32_t)buf * 2 * TILE_B;
        load_tile32(st,          A0 + c * 32, lda, tid);
        load_tile32(st + TILE_B, B0 + c * 32, ldb, tid);
    };

    load_stage(0, 0);
    cp_commit();

    const int arow0 = warp_m * 64 + (lane >> 2);
    const int bcol0 = warp_n * 32 + (lane >> 2);
    const int kq2   = 2 * (lane & 3);

    for (int c = 0; c < nch; c++) {
        if (c + 1 < nch) {
            load_stage((c + 1) & 1, c + 1);
            cp_commit();
            cp_wait<1>();
        } else {
            cp_wait<0>();
        }
        __syncthreads();

        const float* st  = smf + (size_t)(c & 1) * 2 * TILE_F;
        const float* Ath = st;
        const float* Bth = st + TILE_F;

#pragma unroll
        for (int s = 0; s < 4; s++) {
            const int ko = s * 8 + kq2;
            float2 a0[IT], a1[IT], b0[4];
#pragma unroll
            for (int i = 0; i < IT; i++) {
                a0[i] = *reinterpret_cast<const float2*>(
                    Ath + (size_t)(arow0 + i * 16) * LDW + ko);
                a1[i] = *reinterpret_cast<const float2*>(
                    Ath + (size_t)(arow0 + i * 16 + 8) * LDW + ko);
            }
#pragma unroll
            for (int j = 0; j < 4; j++)
                b0[j] = *reinterpret_cast<const float2*>(
                    Bth + (size_t)(bcol0 + j * 8) * LDW + ko);
#pragma unroll
            for (int i = 0; i < IT; i++)
#pragma unroll
                for (int j = 0; j < 4; j++)
                    mma8(acc[i][j], a0[i].x, a1[i].x, a0[i].y, a1[i].y,
                         b0[j].x, b0[j].y);
        }
        __syncthreads();
    }

#pragma unroll
    for (int i = 0; i < IT; i++) {
#pragma unroll
        for (int j = 0; j < 4; j++) {
            const float* a4 = acc[i][j];
            const int r0 = m0 + warp_m * 64 + i * 16 + (lane >> 2);
            const int c0 = n0 + warp_n * 32 + j * 8 + 2 * (lane & 3);
            if (EPI == 1) {        // transposed fp16 VW^T[b][dim][seq], permkb
                __half* Cv = (__half*)C;
                const float bx = bias ? bias[c0] : 0.0f;
                const float by = bias ? bias[c0 + 1] : 0.0f;
                const int b0i = r0 >> 11,        sx0 = permkb(r0 & (SEQ - 1));
                const int b1i = (r0 + 8) >> 11,  sx1 = permkb((r0 + 8) & (SEQ - 1));
                __half* p0 = Cv + (size_t)b0i * DIM * SEQ;
                __half* p1 = Cv + (size_t)b1i * DIM * SEQ;
                p0[(size_t)c0 * SEQ + sx0]       = __float2half(a4[0] + bx);
                p0[(size_t)(c0 + 1) * SEQ + sx0] = __float2half(a4[1] + by);
                p1[(size_t)c0 * SEQ + sx1]       = __float2half(a4[2] + bx);
                p1[(size_t)(c0 + 1) * SEQ + sx1] = __float2half(a4[3] + by);
            } else {               // EPI 5: Wvo^T[n*DIM + permk(m)], fp32
                const int pr0 = permk(r0), pr1 = permk(r0 + 8);
                C[(size_t)c0 * DIM + pr0]       = tf32_rna(a4[0]);
                C[(size_t)(c0 + 1) * DIM + pr0] = tf32_rna(a4[1]);
                C[(size_t)c0 * DIM + pr1]       = tf32_rna(a4[2]);
                C[(size_t)(c0 + 1) * DIM + pr1] = tf32_rna(a4[3]);
            }
        }
    }
}

// ---------------- prep kernels ----------------------------------------------
__global__ void split_all(const float4* __restrict__ q, const float4* __restrict__ kv,
                          __nv_bfloat16* __restrict__ dh,
                          __nv_bfloat16* __restrict__ dl,
                          float* __restrict__ kv32, int n4)
{
    int id = blockIdx.x * 256 + threadIdx.x;
    if (id >= 2 * n4) return;
    const bool is_kv = (id >= n4);
    const float4 v = is_kv ? kv[id - n4] : q[id];
    const int e0 = id * 4;
    const int base = e0 & ~511;
    const float vv[4] = {v.x, v.y, v.z, v.w};
#pragma unroll
    for (int u = 0; u < 4; u++) {
        const int k = (e0 + u) & 511;
        const float x = vv[u];
        const __nv_bfloat16 h = __float2bfloat16(x);
        const int pb = permkb(k);
        dh[base + pb] = h;
        dl[base + pb] = __float2bfloat16(x - __bfloat162float(h));
        if (is_kv) kv32[(base - (int)BND) + permk(k)] = tf32_rna(x);
    }
}

// Wq,Wk: bf16 split transposed (permkb). Wv: non-transposed perm cols (A for
// Wvo gemm). Wo: transposed perm cols (B for Wvo gemm).
__global__ void wprep_all(const float* __restrict__ Wq, const float* __restrict__ Wk,
                          const float* __restrict__ Wv, const float* __restrict__ Wo,
                          __nv_bfloat16* __restrict__ wbh,
                          __nv_bfloat16* __restrict__ wbl,
                          float* __restrict__ wvnt, float* __restrict__ wot)
{
    const int idx = blockIdx.x * 256 + threadIdx.x;
    const int wsel = blockIdx.y;
    const int n = idx & 511;
    const int k = idx >> 9;
    if (wsel < 2) {
        const float w = (wsel ? Wk : Wq)[(size_t)k * DIM + n];
        const __nv_bfloat16 h = __float2bfloat16(w);
        const size_t dst = (size_t)wsel * DIM * DIM + (size_t)n * DIM + permkb(k);
        wbh[dst] = h;
        wbl[dst] = __float2bfloat16(w - __bfloat162float(h));
    } else if (wsel == 2) {        // wvnt[k][permk(n)] = Wv[k][n]
        const float w = Wv[(size_t)k * DIM + n];
        wvnt[(size_t)k * DIM + permk(n)] = tf32_rna(w);
    } else {                       // wot[n][permk(k)] = Wo[k][n]
        const float w = Wo[(size_t)k * DIM + n];
        wot[(size_t)n * DIM + permk(k)] = tf32_rna(w);
    }
}

// bvo[n] = bo[n] + sum_j bv[j] * Wo[j][n]
__global__ void bvo_kernel(const float* __restrict__ bv, const float* __restrict__ Wo,
                           const float* __restrict__ bo, float* __restrict__ bvo)
{
    const int n = blockIdx.x * 256 + threadIdx.x;
    float s = bo[n];
    for (int j = 0; j < DIM; j++) s += bv[j] * Wo[(size_t)j * DIM + n];
    bvo[n] = s;
}

__global__ void __launch_bounds__(256) softmax_rows(const float* __restrict__ S,
                                                    __half* __restrict__ P)
{
    const size_t row = blockIdx.x;
    const float* p = S + row * (size_t)SEQ;
    __half* po = P + row * (size_t)SEQ;
    const int t = threadIdx.x;
    float vals[8];
    float m = -3.402823466e38f;
#pragma unroll
    for (int i = 0; i < 8; i++) { vals[i] = p[t + i * 256]; m = fmaxf(m, vals[i]); }
    __shared__ float red[256];
    red[t] = m; __syncthreads();
#pragma unroll
    for (int s = 128; s > 0; s >>= 1) { if (t < s) red[t] = fmaxf(red[t], red[t+s]); __syncthreads(); }
    m = red[0]; __syncthreads();
    float sum = 0.0f;
#pragma unroll
    for (int i = 0; i < 8; i++) { vals[i] = __expf(vals[i] - m); sum += vals[i]; }
    red[t] = sum; __syncthreads();
#pragma unroll
    for (int s = 128; s > 0; s >>= 1) { if (t < s) red[t] += red[t+s]; __syncthreads(); }
    const float inv = 1.0f / red[0];
#pragma unroll
    for (int i = 0; i < 8; i++) po[t + i * 256] = __float2half(vals[i] * inv);
}

// ---------------- launcher --------------------------------------------------
extern "C" void kernel_launch(void* const* d_in, const int* in_sizes, int n_in,
                              void* d_out, int out_size)
{
    (void)in_sizes; (void)n_in; (void)out_size;
    const float* query     = (const float*)d_in[0];
    const float* key_value = (const float*)d_in[1];
    const float* Wq = (const float*)d_in[2];
    const float* bq = (const float*)d_in[3];
    const float* Wk = (const float*)d_in[4];
    const float* bk = (const float*)d_in[5];
    const float* Wv = (const float*)d_in[6];
    const float* bv = (const float*)d_in[7];
    const float* Wo = (const float*)d_in[8];
    const float* bo = (const float*)d_in[9];
    float* out = (float*)d_out;

    __nv_bfloat16 *in_bh, *in_bl, *qk_bh, *qk_bl, *wbh, *wbl;
    __half *vwt, *pf;
    float *kv_t32, *s, *wvnt, *wot, *wvot, *bvo;
    cudaGetSymbolAddress((void**)&in_bh,  g_in_bh);
    cudaGetSymbolAddress((void**)&in_bl,  g_in_bl);
    cudaGetSymbolAddress((void**)&kv_t32, g_kv_t32);
    cudaGetSymbolAddress((void**)&qk_bh,  g_qk_bh);
    cudaGetSymbolAddress((void**)&qk_bl,  g_qk_bl);
    cudaGetSymbolAddress((void**)&vwt,    g_vwt);
    cudaGetSymbolAddress((void**)&s,      g_s);
    cudaGetSymbolAddress((void**)&pf,     g_pf);
    cudaGetSymbolAddress((void**)&wbh,    g_wqk_bh);
    cudaGetSymbolAddress((void**)&wbl,    g_wqk_bl);
    cudaGetSymbolAddress((void**)&wvnt,   g_wvnt);
    cudaGetSymbolAddress((void**)&wot,    g_wot);
    cudaGetSymbolAddress((void**)&wvot,   g_wvot);
    cudaGetSymbolAddress((void**)&bvo,    g_bvo);

    constexpr int SMB = 2 * 2 * 128 * 160;   // 81920 B
    constexpr int SMH = 2 * 2 * 128 * 80;    // 40960 B
    constexpr int SM1 = 2 * 2 * TILE_B;      // 81920 B
    cudaFuncSetAttribute(gemm_bf16<0>, cudaFuncAttributeMaxDynamicSharedMemorySize, SMB);
    cudaFuncSetAttribute(gemm_bf16<2>, cudaFuncAttributeMaxDynamicSharedMemorySize, SMB);
    cudaFuncSetAttribute(gemm_f16, cudaFuncAttributeMaxDynamicSharedMemorySize, SMH);
    cudaFuncSetAttribute(gemm_t32<1>, cudaFuncAttributeMaxDynamicSharedMemorySize, SM1);
    cudaFuncSetAttribute(gemm_t32<5>, cudaFuncAttributeMaxDynamicSharedMemorySize, SM1);

    const size_t sQKV = (size_t)SEQ * DIM;
    const size_t sS   = (size_t)SEQ * SEQ;
    const size_t sVT  = (size_t)DIM * SEQ;
    const int n4 = (int)(BND / 4);

    split_all<<<(2 * n4) / 256, 256>>>((const float4*)query,
        (const float4*)key_value, in_bh, in_bl, kv_t32, n4);
    {
        dim3 g((DIM * DIM) / 256, 4);
        wprep_all<<<g, 256>>>(Wq, Wk, Wv, Wo, wbh, wbl, wvnt, wot);
    }
    bvo_kernel<<<DIM / 256, 256>>>(bv, Wo, bo, bvo);

    // Wvo^T = (Wv @ Wo)^T (tiny tf32 GEMM)
    {
        dim3 grid(DIM / 128, DIM / 128, 1);
        gemm_t32<5><<<grid, 256, SM1>>>(wvnt, wot, wvot, nullptr,
                                        DIM, DIM, DIM, 0, 0);
    }
    // VW^T = (kv @ Wvo)^T fp16 (tf32 1-pass, transposed epilogue)
    {
        dim3 grid(DIM / 128, (BB * SEQ) / 128, 1);
        gemm_t32<1><<<grid, 256, SM1>>>(kv_t32, wvot, (float*)vwt, nullptr,
                                        DIM, DIM, DIM, 0, 0);
    }
    // q,k projections fused
    {
        dim3 grid(DIM / 128, (BB * SEQ) / 128, 2);
        gemm_bf16<0><<<grid, 256, SMB>>>(in_bh, in_bl, wbh, wbl,
            qk_bh, qk_bl, bq, bk, DIM, DIM, DIM, DIM,
            BND, (size_t)DIM * DIM, BND, 1.0f);
    }
    // S = sqrt(512) * q @ k^T
    {
        dim3 grid(SEQ / 128, SEQ / 128, BB);
        gemm_bf16<2><<<grid, 256, SMB>>>(qk_bh, qk_bl, qk_bh + BND, qk_bl + BND,
            s, nullptr, nullptr, nullptr, DIM, DIM, DIM, SEQ,
            sQKV, sQKV, sS, SCALE_F);
    }
    softmax_rows<<<BB * SEQ, 256>>>(s, pf);
    // out = P @ VW + bvo + query (fp16, final)
    {
        dim3 grid(DIM / 128, SEQ / 128, BB);
        gemm_f16<<<grid, 256, SMH>>>(pf, vwt, out, bvo, query,
                                     SEQ, SEQ, SEQ, DIM, sS, sVT, sQKV);
    }
}

// round 14
// speedup vs baseline: 1.0678x; 1.0678x over previous
#include <cuda_runtime.h>
#include <cuda_bf16.h>
#include <cuda_fp16.h>
#include <cstdint>

// ===========================================================================
// AxisAttention: bf16x3 (m16n8k16) for q/k proj + QK^T; fp16 for P@(VW);
// out-projection folded: Wvo = Wv@Wo (64x64-tile kernel), bvo = bv@Wo + bo,
// out = P @ (kv@Wvo) + bvo + query. B=4, N=2048, D=DA=512.
// ===========================================================================

constexpr int BB  = 4;
constexpr int SEQ = 2048;
constexpr int DIM = 512;
constexpr float SCALE_F = 22.62741699796952f;

constexpr size_t BND = (size_t)BB * SEQ * DIM;

// ---------------- device global scratch -------------------------------------
__device__ __nv_bfloat16 g_in_bh[2 * BND];
__device__ __nv_bfloat16 g_in_bl[2 * BND];
__device__ float         g_kv_t32[BND];
__device__ __nv_bfloat16 g_qk_bh[2 * BND];
__device__ __nv_bfloat16 g_qk_bl[2 * BND];
__device__ __half g_vwt[(size_t)BB * DIM * SEQ];
__device__ float  g_s[(size_t)BB * SEQ * SEQ];
__device__ __half g_pf[(size_t)BB * SEQ * SEQ];
__device__ __nv_bfloat16 g_wqk_bh[2 * DIM * DIM];
__device__ __nv_bfloat16 g_wqk_bl[2 * DIM * DIM];
__device__ float g_wvnt[DIM * DIM];
__device__ float g_wot[DIM * DIM];
__device__ float g_wvot[DIM * DIM];
__device__ float g_bvo[DIM];

// ---------------- helpers ----------------------------------------------------
__device__ __forceinline__ uint32_t smem_u32(const void* p) {
    uint32_t a;
    asm("{ .reg .u64 t; cvta.to.shared.u64 t, %1; cvt.u32.u64 %0, t; }"
        : "=r"(a) : "l"(p));
    return a;
}
__device__ __forceinline__ float tf32_rna(float x) {
    uint32_t u;
    asm("cvt.rna.tf32.f32 %0, %1;" : "=r"(u) : "f"(x));
    return __uint_as_float(u);
}
__device__ __forceinline__ void cp16(uint32_t saddr, const void* g) {
    asm volatile("cp.async.cg.shared.global [%0], [%1], 16;"
                 :: "r"(saddr), "l"(g) : "memory");
}
__device__ __forceinline__ void cp_commit() {
    asm volatile("cp.async.commit_group;" ::: "memory");
}
template <int N>
__device__ __forceinline__ void cp_wait() {
    asm volatile("cp.async.wait_group %0;" :: "n"(N) : "memory");
}

__device__ __forceinline__ int permk(int k) {
    const int lo = k & 7;
    return (k & ~15) | ((k & 8) + 2 * (lo & 3) + (lo >> 2));
}
__device__ __forceinline__ int permkb(int k) {
    const int t = k & 15;
    const int q = (t & 7) >> 1, d = t & 1, e = t >> 3;
    return (k & ~15) | (4 * q + 2 * e + d);
}

__device__ __forceinline__ void mma8(float* c, float a0, float a1, float a2,
                                     float a3, float b0, float b1) {
    asm volatile(
        "mma.sync.aligned.m16n8k8.row.col.f32.tf32.tf32.f32 "
        "{%0,%1,%2,%3}, {%4,%5,%6,%7}, {%8,%9}, {%0,%1,%2,%3};"
        : "+f"(c[0]), "+f"(c[1]), "+f"(c[2]), "+f"(c[3])
        : "r"(__float_as_uint(a0)), "r"(__float_as_uint(a1)),
          "r"(__float_as_uint(a2)), "r"(__float_as_uint(a3)),
          "r"(__float_as_uint(b0)), "r"(__float_as_uint(b1)));
}
__device__ __forceinline__ void mma16(float* c, uint32_t a0, uint32_t a1,
                                      uint32_t a2, uint32_t a3,
                                      uint32_t b0, uint32_t b1) {
    asm volatile(
        "mma.sync.aligned.m16n8k16.row.col.f32.bf16.bf16.f32 "
        "{%0,%1,%2,%3}, {%4,%5,%6,%7}, {%8,%9}, {%0,%1,%2,%3};"
        : "+f"(c[0]), "+f"(c[1]), "+f"(c[2]), "+f"(c[3])
        : "r"(a0), "r"(a1), "r"(a2), "r"(a3), "r"(b0), "r"(b1));
}
__device__ __forceinline__ void mma16h(float* c, uint32_t a0, uint32_t a1,
                                       uint32_t a2, uint32_t a3,
                                       uint32_t b0, uint32_t b1) {
    asm volatile(
        "mma.sync.aligned.m16n8k16.row.col.f32.f16.f16.f32 "
        "{%0,%1,%2,%3}, {%4,%5,%6,%7}, {%8,%9}, {%0,%1,%2,%3};"
        : "+f"(c[0]), "+f"(c[1]), "+f"(c[2]), "+f"(c[3])
        : "r"(a0), "r"(a1), "r"(a2), "r"(a3), "r"(b0), "r"(b1));
}
__device__ __forceinline__ uint32_t f2u(float x) { return __float_as_uint(x); }

// ===========================================================================
// bf16 split GEMM (hh+hl+lh): CTA 128x128, 256 thr occ 2, warp 64x32 (IT=4),
// K-chunk 32. EPI 0: bf16 hi/lo split + bias (staged); EPI 2: alpha fp32
// (permkb cols, staged).
// ===========================================================================
template <int EPI>
__global__ void __launch_bounds__(256, 2) gemm_bf16(
    const __nv_bfloat16* __restrict__ Ahi, const __nv_bfloat16* __restrict__ Alo,
    const __nv_bfloat16* __restrict__ Bhi, const __nv_bfloat16* __restrict__ Blo,
    void* __restrict__ Cp, void* __restrict__ C2p,
    const float* __restrict__ bias, const float* __restrict__ bias2,
    int K, int lda, int ldb, int ldc,
    size_t sA, size_t sB, size_t sC, float alpha)
{
    constexpr int IT = 4, WN = 4;
    constexpr int ROWB  = 160;
    constexpr int TILEB = 128 * ROWB;
    constexpr int STAGEB = 2 * TILEB;

    extern __shared__ char smc[];
    const uint32_t sb = smem_u32(smc);

    const int tid    = threadIdx.x;
    const int lane   = tid & 31;
    const int wid    = tid >> 5;
    const int warp_m = wid >> 2;
    const int warp_n = wid & 3;
    const int q      = lane & 3;
    const int n0 = blockIdx.x * 128;
    const int m0 = blockIdx.y * 128;
    const int z  = blockIdx.z;

    const float* bias_z = (EPI == 0 && z == 1) ? bias2 : bias;

    const __nv_bfloat16* A0 = Ahi + (size_t)z * sA + (size_t)m0 * lda;
    const __nv_bfloat16* A1 = Alo + (size_t)z * sA + (size_t)m0 * lda;
    const __nv_bfloat16* B0 = Bhi + (size_t)z * sB + (size_t)n0 * ldb;
    const __nv_bfloat16* B1 = Blo + (size_t)z * sB + (size_t)n0 * ldb;

    float acc[IT][WN][4];
#pragma unroll
    for (int i = 0; i < IT; i++)
#pragma unroll
        for (int j = 0; j < WN; j++)
#pragma unroll
            for (int l = 0; l < 4; l++) acc[i][j][l] = 0.0f;

    const int nch = K / 32;

    auto load_stage = [&](int buf, int c) {
        const uint32_t st = sb + (uint32_t)buf * STAGEB;
#pragma unroll
        for (int i = 0; i < 8; i++) {
            const int idx = tid + i * 256;
            const int tile = idx >> 10;
            const int w    = idx & 1023;
            const int row  = w >> 3;
            const int h    = (w >> 2) & 1;
            const int cc   = w & 3;
            const __nv_bfloat16* src =
                tile ? (h ? B1 : B0) : (h ? A1 : A0);
            const int ld = tile ? ldb : lda;
            cp16(st + (uint32_t)(tile * TILEB + row * ROWB + h * 64 + cc * 16),
                 src + (size_t)row * ld + c * 32 + cc * 8);
        }
    };

    load_stage(0, 0);
    cp_commit();

    const int arow0 = warp_m * 64 + (lane >> 2);
    const int bcol0 = warp_n * 32 + (lane >> 2);

    for (int c = 0; c < nch; c++) {
        if (c + 1 < nch) {
            load_stage((c + 1) & 1, c + 1);
            cp_commit();
            cp_wait<1>();
        } else {
            cp_wait<0>();
        }
        __syncthreads();

        const char* stg = smc + (size_t)(c & 1) * STAGEB;
        const char* Ab  = stg;
        const char* Bb  = stg + TILEB;

#pragma unroll
        for (int b = 0; b < 2; b++) {
            const int kb = b * 32 + 8 * q;
            float2 Ah0[IT], Ah1[IT];
#pragma unroll
            for (int i = 0; i < IT; i++) {
                const int row = arow0 + i * 16;
                Ah0[i] = *reinterpret_cast<const float2*>(Ab + row * ROWB + kb);
                Ah1[i] = *reinterpret_cast<const float2*>(Ab + (row + 8) * ROWB + kb);
            }
            float2 Bh[WN];
#pragma unroll
            for (int j = 0; j < WN; j++)
                Bh[j] = *reinterpret_cast<const float2*>(
                    Bb + (bcol0 + j * 8) * ROWB + kb);
#pragma unroll
            for (int i = 0; i < IT; i++)
#pragma unroll
                for (int j = 0; j < WN; j++)
                    mma16(acc[i][j], f2u(Ah0[i].x), f2u(Ah1[i].x),
                          f2u(Ah0[i].y), f2u(Ah1[i].y), f2u(Bh[j].x), f2u(Bh[j].y));
            float2 Bl[WN];
#pragma unroll
            for (int j = 0; j < WN; j++)
                Bl[j] = *reinterpret_cast<const float2*>(
                    Bb + (bcol0 + j * 8) * ROWB + 64 + kb);
#pragma unroll
            for (int i = 0; i < IT; i++)
#pragma unroll
                for (int j = 0; j < WN; j++)
                    mma16(acc[i][j], f2u(Ah0[i].x), f2u(Ah1[i].x),
                          f2u(Ah0[i].y), f2u(Ah1[i].y), f2u(Bl[j].x), f2u(Bl[j].y));
            float2 Al0[IT], Al1[IT];
#pragma unroll
            for (int i = 0; i < IT; i++) {
                const int row = arow0 + i * 16;
                Al0[i] = *reinterpret_cast<const float2*>(Ab + row * ROWB + 64 + kb);
                Al1[i] = *reinterpret_cast<const float2*>(Ab + (row + 8) * ROWB + 64 + kb);
            }
#pragma unroll
            for (int i = 0; i < IT; i++)
#pragma unroll
                for (int j = 0; j < WN; j++)
                    mma16(acc[i][j], f2u(Al0[i].x), f2u(Al1[i].x),
                          f2u(Al0[i].y), f2u(Al1[i].y), f2u(Bh[j].x), f2u(Bh[j].y));
        }
        __syncthreads();
    }

    // ---------------- staged epilogues ----------------
    if (EPI == 0) {
        __nv_bfloat16* sh = reinterpret_cast<__nv_bfloat16*>(smc);
        __nv_bfloat16* sl = sh + 128 * 128;
#pragma unroll
        for (int i = 0; i < IT; i++) {
#pragma unroll
            for (int j = 0; j < WN; j++) {
                const float* a4 = acc[i][j];
                const int lr = warp_m * 64 + i * 16 + (lane >> 2);
                const int lc = warp_n * 32 + j * 8 + 2 * q;
                const float bx = bias_z[n0 + lc], by = bias_z[n0 + lc + 1];
                const int p0 = permkb(lc), p1 = permkb(lc + 1);
                const float v[4] = {a4[0] + bx, a4[1] + by, a4[2] + bx, a4[3] + by};
                const int rr[4] = {lr, lr, lr + 8, lr + 8};
                const int pp[4] = {p0, p1, p0, p1};
#pragma unroll
                for (int u = 0; u < 4; u++) {
                    const __nv_bfloat16 h = __float2bfloat16(v[u]);
                    sh[rr[u] * 128 + pp[u]] = h;
                    sl[rr[u] * 128 + pp[u]] =
                        __float2bfloat16(v[u] - __bfloat162float(h));
                }
            }
        }
        __syncthreads();
        __nv_bfloat16* Cz  = (__nv_bfloat16*)Cp  + (size_t)z * sC;
        __nv_bfloat16* C2z = (__nv_bfloat16*)C2p + (size_t)z * sC;
#pragma unroll
        for (int t = 0; t < 8; t++) {
            const int idx = tid + t * 256;
            const int row = idx >> 4;
            const int c16 = idx & 15;
            *reinterpret_cast<uint4*>(Cz + (size_t)(m0 + row) * ldc + n0 + c16 * 8) =
                *reinterpret_cast<const uint4*>(sh + row * 128 + c16 * 8);
            *reinterpret_cast<uint4*>(C2z + (size_t)(m0 + row) * ldc + n0 + c16 * 8) =
                *reinterpret_cast<const uint4*>(sl + row * 128 + c16 * 8);
        }
    } else {
        float* ss = reinterpret_cast<float*>(smc);
#pragma unroll
        for (int i = 0; i < IT; i++) {
#pragma unroll
            for (int j = 0; j < WN; j++) {
                const float* a4 = acc[i][j];
                const int lr = warp_m * 64 + i * 16 + (lane >> 2);
                const int lc = warp_n * 32 + j * 8 + 2 * q;
                const int p0 = permkb(lc), p1 = permkb(lc + 1);
                ss[lr * 128 + p0]       = alpha * a4[0];
                ss[lr * 128 + p1]       = alpha * a4[1];
                ss[(lr + 8) * 128 + p0] = alpha * a4[2];
                ss[(lr + 8) * 128 + p1] = alpha * a4[3];
            }
        }
        __syncthreads();
        float* Cz = (float*)Cp + (size_t)z * sC;
#pragma unroll
        for (int t = 0; t < 16; t++) {
            const int idx = tid + t * 256;
            const int row = idx >> 5;
            const int c8  = idx & 31;
            *reinterpret_cast<uint4*>(Cz + (size_t)(m0 + row) * ldc + n0 + c8 * 4) =
                *reinterpret_cast<const uint4*>(ss + row * 128 + c8 * 4);
        }
    }
}

// ===========================================================================
// fp16 single-pass GEMM (final): out = P @ VW + bvo[n] + query[m,n].
// ===========================================================================
__global__ void __launch_bounds__(256, 2) gemm_f16(
    const __half* __restrict__ A, const __half* __restrict__ B,
    float* __restrict__ C,
    const float* __restrict__ bias, const float* __restrict__ resid,
    int K, int lda, int ldb, int ldc,
    size_t sA, size_t sB, size_t sC)
{
    constexpr int IT = 4;
    constexpr int ROWB  = 80;
    constexpr int TILEB = 128 * ROWB;
    constexpr int STAGEB = 2 * TILEB;

    extern __shared__ char smc[];
    const uint32_t sb = smem_u32(smc);

    const int tid    = threadIdx.x;
    const int lane   = tid & 31;
    const int wid    = tid >> 5;
    const int warp_m = wid >> 2;
    const int warp_n = wid & 3;
    const int q      = lane & 3;
    const int n0 = blockIdx.x * 128;
    const int m0 = blockIdx.y * 128;
    const int z  = blockIdx.z;

    const __half* A0 = A + (size_t)z * sA + (size_t)m0 * lda;
    const __half* B0 = B + (size_t)z * sB + (size_t)n0 * ldb;

    float acc[IT][4][4];
#pragma unroll
    for (int i = 0; i < IT; i++)
#pragma unroll
        for (int j = 0; j < 4; j++)
#pragma unroll
            for (int l = 0; l < 4; l++) acc[i][j][l] = 0.0f;

    const int nch = K / 32;

    auto load_stage = [&](int buf, int c) {
        const uint32_t st = sb + (uint32_t)buf * STAGEB;
#pragma unroll
        for (int i = 0; i < 4; i++) {
            const int idx = tid + i * 256;
            const int tile = idx >> 9;
            const int w    = idx & 511;
            const int row  = w >> 2;
            const int cc   = w & 3;
            const __half* src = tile ? B0 : A0;
            const int ld = tile ? ldb : lda;
            cp16(st + (uint32_t)(tile * TILEB + row * ROWB + cc * 16),
                 src + (size_t)row * ld + c * 32 + cc * 8);
        }
    };

    load_stage(0, 0);
    cp_commit();

    const int arow0 = warp_m * 64 + (lane >> 2);
    const int bcol0 = warp_n * 32 + (lane >> 2);

    for (int c = 0; c < nch; c++) {
        if (c + 1 < nch) {
            load_stage((c + 1) & 1, c + 1);
            cp_commit();
            cp_wait<1>();
        } else {
            cp_wait<0>();
        }
        __syncthreads();

        const char* stg = smc + (size_t)(c & 1) * STAGEB;
        const char* Ab  = stg;
        const char* Bb  = stg + TILEB;

#pragma unroll
        for (int b = 0; b < 2; b++) {
            const int kb = b * 32 + 8 * q;
            float2 a0[IT], a1[IT], b0[4];
#pragma unroll
            for (int i = 0; i < IT; i++) {
                const int row = arow0 + i * 16;
                a0[i] = *reinterpret_cast<const float2*>(Ab + row * ROWB + kb);
                a1[i] = *reinterpret_cast<const float2*>(Ab + (row + 8) * ROWB + kb);
            }
#pragma unroll
            for (int j = 0; j < 4; j++)
                b0[j] = *reinterpret_cast<const float2*>(
                    Bb + (bcol0 + j * 8) * ROWB + kb);
#pragma unroll
            for (int i = 0; i < IT; i++)
#pragma unroll
                for (int j = 0; j < 4; j++)
                    mma16h(acc[i][j], f2u(a0[i].x), f2u(a1[i].x),
                           f2u(a0[i].y), f2u(a1[i].y), f2u(b0[j].x), f2u(b0[j].y));
        }
        __syncthreads();
    }

    float* Cz = C + (size_t)z * sC;
    const float* Rz = resid + (size_t)z * sC;
#pragma unroll
    for (int i = 0; i < IT; i++) {
#pragma unroll
        for (int j = 0; j < 4; j++) {
            const float* a4 = acc[i][j];
            const int r0 = m0 + warp_m * 64 + i * 16 + (lane >> 2);
            const int c0 = n0 + warp_n * 32 + j * 8 + 2 * q;
            const float bx = bias[c0], by = bias[c0 + 1];
            const float2 rs0 = *reinterpret_cast<const float2*>(
                &Rz[(size_t)r0 * ldc + c0]);
            const float2 rs1 = *reinterpret_cast<const float2*>(
                &Rz[(size_t)(r0 + 8) * ldc + c0]);
            float2 v0, v1;
            v0.x = a4[0] + bx + rs0.x; v0.y = a4[1] + by + rs0.y;
            v1.x = a4[2] + bx + rs1.x; v1.y = a4[3] + by + rs1.y;
            *reinterpret_cast<float2*>(&Cz[(size_t)r0 * ldc + c0]) = v0;
            *reinterpret_cast<float2*>(&Cz[(size_t)(r0 + 8) * ldc + c0]) = v1;
        }
    }
}

// ===========================================================================
// tf32 1-pass GEMM (VW^T): CTA 128x128, 256 thr occ 2, warp 64x32, K-chunk 32.
// Transposed fp16 output (permkb seq).
// ===========================================================================
constexpr int LDW    = 40;
constexpr int TILE_F = 128 * LDW;
constexpr int TILE_B = TILE_F * 4;

__device__ __forceinline__ void load_tile32(
    uint32_t sbase, const float* __restrict__ g, int ld, int tid)
{
#pragma unroll
    for (int i = 0; i < 4; i++) {
        const int f  = tid + i * 256;
        const int r  = f >> 3;
        const int c4 = (f & 7) << 2;
        cp16(sbase + (uint32_t)(r * LDW + c4) * 4, g + (size_t)r * ld + c4);
    }
}

__global__ void __launch_bounds__(256, 2) gemm_t32_vw(
    const float* __restrict__ A, const float* __restrict__ B,
    __half* __restrict__ C, int K, int lda, int ldb)
{
    constexpr int IT = 4;
    extern __shared__ float smf[];
    const uint32_t sb = smem_u32(smf);

    const int tid    = threadIdx.x;
    const int lane   = tid & 31;
    const int wid    = tid >> 5;
    const int warp_m = wid >> 2;
    const int warp_n = wid & 3;
    const int n0 = blockIdx.x * 128;
    const int m0 = blockIdx.y * 128;

    const float* A0 = A + (size_t)m0 * lda;
    const float* B0 = B + (size_t)n0 * ldb;

    float acc[IT][4][4];
#pragma unroll
    for (int i = 0; i < IT; i++)
#pragma unroll
        for (int j = 0; j < 4; j++)
#pragma unroll
            for (int l = 0; l < 4; l++) acc[i][j][l] = 0.0f;

    const int nch = K / 32;

    auto load_stage = [&](int buf, int c) {
        const uint32_t st = sb + (uint32_t)buf * 2 * TILE_B;
        load_tile32(st,          A0 + c * 32, lda, tid);
        load_tile32(st + TILE_B, B0 + c * 32, ldb, tid);
    };

    load_stage(0, 0);
    cp_commit();

    const int arow0 = warp_m * 64 + (lane >> 2);
    const int bcol0 = warp_n * 32 + (lane >> 2);
    const int kq2   = 2 * (lane & 3);

    for (int c = 0; c < nch; c++) {
        if (c + 1 < nch) {
            load_stage((c + 1) & 1, c + 1);
            cp_commit();
            cp_wait<1>();
        } else {
            cp_wait<0>();
        }
        __syncthreads();

        const float* st  = smf + (size_t)(c & 1) * 2 * TILE_F;
        const float* Ath = st;
        const float* Bth = st + TILE_F;

#pragma unroll
        for (int s = 0; s < 4; s++) {
            const int ko = s * 8 + kq2;
            float2 a0[IT], a1[IT], b0[4];
#pragma unroll
            for (int i = 0; i < IT; i++) {
                a0[i] = *reinterpret_cast<const float2*>(
                    Ath + (size_t)(arow0 + i * 16) * LDW + ko);
                a1[i] = *reinterpret_cast<const float2*>(
                    Ath + (size_t)(arow0 + i * 16 + 8) * LDW + ko);
            }
#pragma unroll
            for (int j = 0; j < 4; j++)
                b0[j] = *reinterpret_cast<const float2*>(
                    Bth + (size_t)(bcol0 + j * 8) * LDW + ko);
#pragma unroll
            for (int i = 0; i < IT; i++)
#pragma unroll
                for (int j = 0; j < 4; j++)
                    mma8(acc[i][j], a0[i].x, a1[i].x, a0[i].y, a1[i].y,
                         b0[j].x, b0[j].y);
        }
        __syncthreads();
    }

#pragma unroll
    for (int i = 0; i < IT; i++) {
#pragma unroll
        for (int j = 0; j < 4; j++) {
            const float* a4 = acc[i][j];
            const int r0 = m0 + warp_m * 64 + i * 16 + (lane >> 2);
            const int c0 = n0 + warp_n * 32 + j * 8 + 2 * (lane & 3);
            const int b0i = r0 >> 11,        sx0 = permkb(r0 & (SEQ - 1));
            const int b1i = (r0 + 8) >> 11,  sx1 = permkb((r0 + 8) & (SEQ - 1));
            __half* p0 = C + (size_t)b0i * DIM * SEQ;
            __half* p1 = C + (size_t)b1i * DIM * SEQ;
            p0[(size_t)c0 * SEQ + sx0]       = __float2half(a4[0]);
            p0[(size_t)(c0 + 1) * SEQ + sx0] = __float2half(a4[1]);
            p1[(size_t)c0 * SEQ + sx1]       = __float2half(a4[2]);
            p1[(size_t)(c0 + 1) * SEQ + sx1] = __float2half(a4[3]);
        }
    }
}

// ===========================================================================
// Wvo GEMM: 64x64 CTA tile (grid 8x8 = 64 CTAs), 256 thr, warp 32x16,
// K=512, tf32. Writes Wvo^T[n*DIM + permk(m)].
// ===========================================================================
__global__ void __launch_bounds__(256, 2) gemm_wvo(
    const float* __restrict__ A, const float* __restrict__ B,
    float* __restrict__ C)
{
    constexpr int T64F = 64 * LDW;       // 2560 floats
    constexpr int T64B = T64F * 4;       // 10240 B
    extern __shared__ float smf[];
    const uint32_t sb = smem_u32(smf);

    const int tid    = threadIdx.x;
    const int lane   = tid & 31;
    const int wid    = tid >> 5;
    const int warp_m = wid >> 2;       // 0..1
    const int warp_n = wid & 3;        // 0..3
    const int n0 = blockIdx.x * 64;
    const int m0 = blockIdx.y * 64;

    const float* A0 = A + (size_t)m0 * DIM;
    const float* B0 = B + (size_t)n0 * DIM;

    float acc[2][2][4];
#pragma unroll
    for (int i = 0; i < 2; i++)
#pragma unroll
        for (int j = 0; j < 2; j++)
#pragma unroll
            for (int l = 0; l < 4; l++) acc[i][j][l] = 0.0f;

    auto load_stage = [&](int buf, int c) {
        const uint32_t st = sb + (uint32_t)buf * 2 * T64B;
#pragma unroll
        for (int i = 0; i < 4; i++) {
            const int f = tid + i * 256;           // 0..1023
            const int tile = f >> 9;
            const int w = f & 511;
            const int r  = w >> 3;
            const int c4 = (w & 7) << 2;
            const float* src = tile ? B0 : A0;
            cp16(st + (uint32_t)(tile * T64B) + (uint32_t)(r * LDW + c4) * 4,
                 src + (size_t)r * DIM + c * 32 + c4);
        }
    };

    load_stage(0, 0);
    cp_commit();

    const int arow0 = warp_m * 32 + (lane >> 2);
    const int bcol0 = warp_n * 16 + (lane >> 2);
    const int kq2   = 2 * (lane & 3);

    for (int c = 0; c < 16; c++) {
        if (c + 1 < 16) {
            load_stage((c + 1) & 1, c + 1);
            cp_commit();
            cp_wait<1>();
        } else {
            cp_wait<0>();
        }
        __syncthreads();

        const float* st  = smf + (size_t)(c & 1) * 2 * T64F;
        const float* Ath = st;
        const float* Bth = st + T64F;

#pragma unroll
        for (int s = 0; s < 4; s++) {
            const int ko = s * 8 + kq2;
            float2 a0[2], a1[2], b0[2];
#pragma unroll
            for (int i = 0; i < 2; i++) {
                a0[i] = *reinterpret_cast<const float2*>(
                    Ath + (size_t)(arow0 + i * 16) * LDW + ko);
                a1[i] = *reinterpret_cast<const float2*>(
                    Ath + (size_t)(arow0 + i * 16 + 8) * LDW + ko);
            }
#pragma unroll
            for (int j = 0; j < 2; j++)
                b0[j] = *reinterpret_cast<const float2*>(
                    Bth + (size_t)(bcol0 + j * 8) * LDW + ko);
#pragma unroll
            for (int i = 0; i < 2; i++)
#pragma unroll
                for (int j = 0; j < 2; j++)
                    mma8(acc[i][j], a0[i].x, a1[i].x, a0[i].y, a1[i].y,
                         b0[j].x, b0[j].y);
        }
        __syncthreads();
    }

#pragma unroll
    for (int i = 0; i < 2; i++) {
#pragma unroll
        for (int j = 0; j < 2; j++) {
            const float* a4 = acc[i][j];
            const int r0 = m0 + warp_m * 32 + i * 16 + (lane >> 2);
            const int c0 = n0 + warp_n * 16 + j * 8 + 2 * (lane & 3);
            const int pr0 = permk(r0), pr1 = permk(r0 + 8);
            C[(size_t)c0 * DIM + pr0]       = tf32_rna(a4[0]);
            C[(size_t)(c0 + 1) * DIM + pr0] = tf32_rna(a4[1]);
            C[(size_t)c0 * DIM + pr1]       = tf32_rna(a4[2]);
            C[(size_t)(c0 + 1) * DIM + pr1] = tf32_rna(a4[3]);
        }
    }
}

// ---------------- prep kernels ----------------------------------------------
__global__ void split_all(const float4* __restrict__ q, const float4* __restrict__ kv,
                          __nv_bfloat16* __restrict__ dh,
                          __nv_bfloat16* __restrict__ dl,
                          float* __restrict__ kv32, int n4)
{
    int id = blockIdx.x * 256 + threadIdx.x;
    if (id >= 2 * n4) return;
    const bool is_kv = (id >= n4);
    const float4 v = is_kv ? kv[id - n4] : q[id];
    const int e0 = id * 4;
    const int base = e0 & ~511;
    const float vv[4] = {v.x, v.y, v.z, v.w};
#pragma unroll
    for (int u = 0; u < 4; u++) {
        const int k = (e0 + u) & 511;
        const float x = vv[u];
        const __nv_bfloat16 h = __float2bfloat16(x);
        const int pb = permkb(k);
        dh[base + pb] = h;
        dl[base + pb] = __float2bfloat16(x - __bfloat162float(h));
        if (is_kv) kv32[(base - (int)BND) + permk(k)] = tf32_rna(x);
    }
}

__global__ void wprep_all(const float* __restrict__ Wq, const float* __restrict__ Wk,
                          const float* __restrict__ Wv, const float* __restrict__ Wo,
                          __nv_bfloat16* __restrict__ wbh,
                          __nv_bfloat16* __restrict__ wbl,
                          float* __restrict__ wvnt, float* __restrict__ wot)
{
    const int idx = blockIdx.x * 256 + threadIdx.x;
    const int wsel = blockIdx.y;
    const int n = idx & 511;
    const int k = idx >> 9;
    if (wsel < 2) {
        const float w = (wsel ? Wk : Wq)[(size_t)k * DIM + n];
        const __nv_bfloat16 h = __float2bfloat16(w);
        const size_t dst = (size_t)wsel * DIM * DIM + (size_t)n * DIM + permkb(k);
        wbh[dst] = h;
        wbl[dst] = __float2bfloat16(w - __bfloat162float(h));
    } else if (wsel == 2) {
        const float w = Wv[(size_t)k * DIM + n];
        wvnt[(size_t)k * DIM + permk(n)] = tf32_rna(w);
    } else {
        const float w = Wo[(size_t)k * DIM + n];
        wot[(size_t)n * DIM + permk(k)] = tf32_rna(w);
    }
}

// bvo[n] = bo[n] + sum_j bv[j]*Wo[j][n]; grid 8, 4-way k-split, smem reduce
__global__ void bvo_kernel(const float* __restrict__ bv, const float* __restrict__ Wo,
                           const float* __restrict__ bo, float* __restrict__ bvo)
{
    __shared__ float red[256];
    const int tid = threadIdx.x;
    const int n = blockIdx.x * 64 + (tid & 63);
    const int part = tid >> 6;
    float s = 0.0f;
    for (int j = part * 128; j < part * 128 + 128; j++)
        s += bv[j] * Wo[(size_t)j * DIM + n];
    red[tid] = s;
    __syncthreads();
    if (tid < 64)
        bvo[n] = bo[n] + red[tid] + red[tid + 64] + red[tid + 128] + red[tid + 192];
}

// ---------------- softmax: float4 loads, warp-shuffle reductions ------------
__global__ void __launch_bounds__(256) softmax_rows(const float* __restrict__ S,
                                                    __half* __restrict__ P)
{
    const size_t row = blockIdx.x;
    const float4* p4 = reinterpret_cast<const float4*>(S + row * (size_t)SEQ);
    __half2* po2 = reinterpret_cast<__half2*>(P + row * (size_t)SEQ);
    const int t = threadIdx.x;
    const int lane = t & 31;
    const int wid  = t >> 5;

    float4 v0 = p4[t];
    float4 v1 = p4[t + 256];
    float m = fmaxf(fmaxf(fmaxf(v0.x, v0.y), fmaxf(v0.z, v0.w)),
                    fmaxf(fmaxf(v1.x, v1.y), fmaxf(v1.z, v1.w)));
#pragma unroll
    for (int o = 16; o > 0; o >>= 1)
        m = fmaxf(m, __shfl_xor_sync(0xFFFFFFFFu, m, o));
    __shared__ float wred[8];
    if (lane == 0) wred[wid] = m;
    __syncthreads();
    m = wred[0];
#pragma unroll
    for (int w = 1; w < 8; w++) m = fmaxf(m, wred[w]);

    v0.x = __expf(v0.x - m); v0.y = __expf(v0.y - m);
    v0.z = __expf(v0.z - m); v0.w = __expf(v0.w - m);
    v1.x = __expf(v1.x - m); v1.y = __expf(v1.y - m);
    v1.z = __expf(v1.z - m); v1.w = __expf(v1.w - m);
    float sum = (v0.x + v0.y) + (v0.z + v0.w) + (v1.x + v1.y) + (v1.z + v1.w);
#pragma unroll
    for (int o = 16; o > 0; o >>= 1)
        sum += __shfl_xor_sync(0xFFFFFFFFu, sum, o);
    __shared__ float wsum[8];
    if (lane == 0) wsum[wid] = sum;
    __syncthreads();
    sum = wsum[0];
#pragma unroll
    for (int w = 1; w < 8; w++) sum += wsum[w];
    const float inv = 1.0f / sum;

    po2[2 * t + 0]   = __floats2half2_rn(v0.x * inv, v0.y * inv);
    po2[2 * t + 1]   = __floats2half2_rn(v0.z * inv, v0.w * inv);
    po2[2 * (t + 256) + 0] = __floats2half2_rn(v1.x * inv, v1.y * inv);
    po2[2 * (t + 256) + 1] = __floats2half2_rn(v1.z * inv, v1.w * inv);
}

// ---------------- launcher --------------------------------------------------
extern "C" void kernel_launch(void* const* d_in, const int* in_sizes, int n_in,
                              void* d_out, int out_size)
{
    (void)in_sizes; (void)n_in; (void)out_size;
    const float* query     = (const float*)d_in[0];
    const float* key_value = (const float*)d_in[1];
    const float* Wq = (const float*)d_in[2];
    const float* bq = (const float*)d_in[3];
    const float* Wk = (const float*)d_in[4];
    const float* bk = (const float*)d_in[5];
    const float* Wv = (const float*)d_in[6];
    const float* bv = (const float*)d_in[7];
    const float* Wo = (const float*)d_in[8];
    const float* bo = (const float*)d_in[9];
    float* out = (float*)d_out;

    __nv_bfloat16 *in_bh, *in_bl, *qk_bh, *qk_bl, *wbh, *wbl;
    __half *vwt, *pf;
    float *kv_t32, *s, *wvnt, *wot, *wvot, *bvo;
    cudaGetSymbolAddress((void**)&in_bh,  g_in_bh);
    cudaGetSymbolAddress((void**)&in_bl,  g_in_bl);
    cudaGetSymbolAddress((void**)&kv_t32, g_kv_t32);
    cudaGetSymbolAddress((void**)&qk_bh,  g_qk_bh);
    cudaGetSymbolAddress((void**)&qk_bl,  g_qk_bl);
    cudaGetSymbolAddress((void**)&vwt,    g_vwt);
    cudaGetSymbolAddress((void**)&s,      g_s);
    cudaGetSymbolAddress((void**)&pf,     g_pf);
    cudaGetSymbolAddress((void**)&wbh,    g_wqk_bh);
    cudaGetSymbolAddress((void**)&wbl,    g_wqk_bl);
    cudaGetSymbolAddress((void**)&wvnt,   g_wvnt);
    cudaGetSymbolAddress((void**)&wot,    g_wot);
    cudaGetSymbolAddress((void**)&wvot,   g_wvot);
    cudaGetSymbolAddress((void**)&bvo,    g_bvo);

    constexpr int SMB = 2 * 2 * 128 * 160;   // 81920 B
    constexpr int SMH = 2 * 2 * 128 * 80;    // 40960 B
    constexpr int SM1 = 2 * 2 * TILE_B;      // 81920 B
    constexpr int SMW = 2 * 2 * 64 * LDW * 4; // 40960 B
    cudaFuncSetAttribute(gemm_bf16<0>, cudaFuncAttributeMaxDynamicSharedMemorySize, SMB);
    cudaFuncSetAttribute(gemm_bf16<2>, cudaFuncAttributeMaxDynamicSharedMemorySize, SMB);
    cudaFuncSetAttribute(gemm_f16, cudaFuncAttributeMaxDynamicSharedMemorySize, SMH);
    cudaFuncSetAttribute(gemm_t32_vw, cudaFuncAttributeMaxDynamicSharedMemorySize, SM1);
    cudaFuncSetAttribute(gemm_wvo, cudaFuncAttributeMaxDynamicSharedMemorySize, SMW);

    const size_t sQKV = (size_t)SEQ * DIM;
    const size_t sS   = (size_t)SEQ * SEQ;
    const size_t sVT  = (size_t)DIM * SEQ;
    const int n4 = (int)(BND / 4);

    split_all<<<(2 * n4) / 256, 256>>>((const float4*)query,
        (const float4*)key_value, in_bh, in_bl, kv_t32, n4);
    {
        dim3 g((DIM * DIM) / 256, 4);
        wprep_all<<<g, 256>>>(Wq, Wk, Wv, Wo, wbh, wbl, wvnt, wot);
    }
    bvo_kernel<<<DIM / 64, 256>>>(bv, Wo, bo, bvo);

    // Wvo^T = (Wv @ Wo)^T (64x64 tiles, 64 CTAs)
    gemm_wvo<<<dim3(8, 8), 256, SMW>>>(wvnt, wot, wvot);

    // VW^T = (kv @ Wvo)^T fp16
    {
        dim3 grid(DIM / 128, (BB * SEQ) / 128, 1);
        gemm_t32_vw<<<grid, 256, SM1>>>(kv_t32, wvot, vwt, DIM, DIM, DIM);
    }
    // q,k projections fused
    {
        dim3 grid(DIM / 128, (BB * SEQ) / 128, 2);
        gemm_bf16<0><<<grid, 256, SMB>>>(in_bh, in_bl, wbh, wbl,
            qk_bh, qk_bl, bq, bk, DIM, DIM, DIM, DIM,
            BND, (size_t)DIM * DIM, BND, 1.0f);
    }
    // S = sqrt(512) * q @ k^T
    {
        dim3 grid(SEQ / 128, SEQ / 128, BB);
        gemm_bf16<2><<<grid, 256, SMB>>>(qk_bh, qk_bl, qk_bh + BND, qk_bl + BND,
            s, nullptr, nullptr, nullptr, DIM, DIM, DIM, SEQ,
            sQKV, sQKV, sS, SCALE_F);
    }
    softmax_rows<<<BB * SEQ, 256>>>(s, pf);
    // out = P @ VW + bvo + query (fp16, final)
    {
        dim3 grid(DIM / 128, SEQ / 128, BB);
        gemm_f16<<<grid, 256, SMH>>>(pf, vwt, out, bvo, query,
                                     SEQ, SEQ, SEQ, DIM, sS, sVT, sQKV);
    }
}

// round 15
// speedup vs baseline: 1.1788x; 1.1039x over previous
#include <cuda_runtime.h>
#include <cuda_bf16.h>
#include <cuda_fp16.h>
#include <cstdint>

// ===========================================================================
// AxisAttention: bf16x3 (m16n8k16) for q/k proj + QK^T; fp16 for P@(VW);
// out-projection folded: Wvo = Wv@Wo, bvo = bv@Wo + bo,
// out = P @ (kv@Wvo) + bvo + query.  Two-stream graph: the VW chain
// (kv32/wprep_vo/Wvo/bvo/VW) overlaps the proj/QK^T/softmax chain.
// B=4, N=2048, D=DA=512.
// ===========================================================================

constexpr int BB  = 4;
constexpr int SEQ = 2048;
constexpr int DIM = 512;
constexpr float SCALE_F = 22.62741699796952f;

constexpr size_t BND = (size_t)BB * SEQ * DIM;

// ---------------- device global scratch -------------------------------------
__device__ __nv_bfloat16 g_in_bh[2 * BND];
__device__ __nv_bfloat16 g_in_bl[2 * BND];
__device__ float         g_kv_t32[BND];
__device__ __nv_bfloat16 g_qk_bh[2 * BND];
__device__ __nv_bfloat16 g_qk_bl[2 * BND];
__device__ __half g_vwt[(size_t)BB * DIM * SEQ];
__device__ float  g_s[(size_t)BB * SEQ * SEQ];
__device__ __half g_pf[(size_t)BB * SEQ * SEQ];
__device__ __nv_bfloat16 g_wqk_bh[2 * DIM * DIM];
__device__ __nv_bfloat16 g_wqk_bl[2 * DIM * DIM];
__device__ float g_wvnt[DIM * DIM];
__device__ float g_wot[DIM * DIM];
__device__ float g_wvot[DIM * DIM];
__device__ float g_bvo[DIM];

// ---------------- helpers ----------------------------------------------------
__device__ __forceinline__ uint32_t smem_u32(const void* p) {
    uint32_t a;
    asm("{ .reg .u64 t; cvta.to.shared.u64 t, %1; cvt.u32.u64 %0, t; }"
        : "=r"(a) : "l"(p));
    return a;
}
__device__ __forceinline__ float tf32_rna(float x) {
    uint32_t u;
    asm("cvt.rna.tf32.f32 %0, %1;" : "=r"(u) : "f"(x));
    return __uint_as_float(u);
}
__device__ __forceinline__ void cp16(uint32_t saddr, const void* g) {
    asm volatile("cp.async.cg.shared.global [%0], [%1], 16;"
                 :: "r"(saddr), "l"(g) : "memory");
}
__device__ __forceinline__ void cp_commit() {
    asm volatile("cp.async.commit_group;" ::: "memory");
}
template <int N>
__device__ __forceinline__ void cp_wait() {
    asm volatile("cp.async.wait_group %0;" :: "n"(N) : "memory");
}

__device__ __forceinline__ int permk(int k) {
    const int lo = k & 7;
    return (k & ~15) | ((k & 8) + 2 * (lo & 3) + (lo >> 2));
}
__device__ __forceinline__ int permkb(int k) {
    const int t = k & 15;
    const int q = (t & 7) >> 1, d = t & 1, e = t >> 3;
    return (k & ~15) | (4 * q + 2 * e + d);
}

__device__ __forceinline__ void mma8(float* c, float a0, float a1, float a2,
                                     float a3, float b0, float b1) {
    asm volatile(
        "mma.sync.aligned.m16n8k8.row.col.f32.tf32.tf32.f32 "
        "{%0,%1,%2,%3}, {%4,%5,%6,%7}, {%8,%9}, {%0,%1,%2,%3};"
        : "+f"(c[0]), "+f"(c[1]), "+f"(c[2]), "+f"(c[3])
        : "r"(__float_as_uint(a0)), "r"(__float_as_uint(a1)),
          "r"(__float_as_uint(a2)), "r"(__float_as_uint(a3)),
          "r"(__float_as_uint(b0)), "r"(__float_as_uint(b1)));
}
__device__ __forceinline__ void mma16(float* c, uint32_t a0, uint32_t a1,
                                      uint32_t a2, uint32_t a3,
                                      uint32_t b0, uint32_t b1) {
    asm volatile(
        "mma.sync.aligned.m16n8k16.row.col.f32.bf16.bf16.f32 "
        "{%0,%1,%2,%3}, {%4,%5,%6,%7}, {%8,%9}, {%0,%1,%2,%3};"
        : "+f"(c[0]), "+f"(c[1]), "+f"(c[2]), "+f"(c[3])
        : "r"(a0), "r"(a1), "r"(a2), "r"(a3), "r"(b0), "r"(b1));
}
__device__ __forceinline__ void mma16h(float* c, uint32_t a0, uint32_t a1,
                                       uint32_t a2, uint32_t a3,
                                       uint32_t b0, uint32_t b1) {
    asm volatile(
        "mma.sync.aligned.m16n8k16.row.col.f32.f16.f16.f32 "
        "{%0,%1,%2,%3}, {%4,%5,%6,%7}, {%8,%9}, {%0,%1,%2,%3};"
        : "+f"(c[0]), "+f"(c[1]), "+f"(c[2]), "+f"(c[3])
        : "r"(a0), "r"(a1), "r"(a2), "r"(a3), "r"(b0), "r"(b1));
}
__device__ __forceinline__ uint32_t f2u(float x) { return __float_as_uint(x); }

// ===========================================================================
// bf16 split GEMM (hh+hl+lh): CTA 128x128, 256 thr occ 2, warp 64x32 (IT=4),
// K-chunk 32. EPI 0: bf16 hi/lo split + bias (staged); EPI 2: alpha fp32
// (permkb cols, staged).
// ===========================================================================
template <int EPI>
__global__ void __launch_bounds__(256, 2) gemm_bf16(
    const __nv_bfloat16* __restrict__ Ahi, const __nv_bfloat16* __restrict__ Alo,
    const __nv_bfloat16* __restrict__ Bhi, const __nv_bfloat16* __restrict__ Blo,
    void* __restrict__ Cp, void* __restrict__ C2p,
    const float* __restrict__ bias, const float* __restrict__ bias2,
    int K, int lda, int ldb, int ldc,
    size_t sA, size_t sB, size_t sC, float alpha)
{
    constexpr int IT = 4, WN = 4;
    constexpr int ROWB  = 160;
    constexpr int TILEB = 128 * ROWB;
    constexpr int STAGEB = 2 * TILEB;

    extern __shared__ char smc[];
    const uint32_t sb = smem_u32(smc);

    const int tid    = threadIdx.x;
    const int lane   = tid & 31;
    const int wid    = tid >> 5;
    const int warp_m = wid >> 2;
    const int warp_n = wid & 3;
    const int q      = lane & 3;
    const int n0 = blockIdx.x * 128;
    const int m0 = blockIdx.y * 128;
    const int z  = blockIdx.z;

    const float* bias_z = (EPI == 0 && z == 1) ? bias2 : bias;

    const __nv_bfloat16* A0 = Ahi + (size_t)z * sA + (size_t)m0 * lda;
    const __nv_bfloat16* A1 = Alo + (size_t)z * sA + (size_t)m0 * lda;
    const __nv_bfloat16* B0 = Bhi + (size_t)z * sB + (size_t)n0 * ldb;
    const __nv_bfloat16* B1 = Blo + (size_t)z * sB + (size_t)n0 * ldb;

    float acc[IT][WN][4];
#pragma unroll
    for (int i = 0; i < IT; i++)
#pragma unroll
        for (int j = 0; j < WN; j++)
#pragma unroll
            for (int l = 0; l < 4; l++) acc[i][j][l] = 0.0f;

    const int nch = K / 32;

    auto load_stage = [&](int buf, int c) {
        const uint32_t st = sb + (uint32_t)buf * STAGEB;
#pragma unroll
        for (int i = 0; i < 8; i++) {
            const int idx = tid + i * 256;
            const int tile = idx >> 10;
            const int w    = idx & 1023;
            const int row  = w >> 3;
            const int h    = (w >> 2) & 1;
            const int cc   = w & 3;
            const __nv_bfloat16* src =
                tile ? (h ? B1 : B0) : (h ? A1 : A0);
            const int ld = tile ? ldb : lda;
            cp16(st + (uint32_t)(tile * TILEB + row * ROWB + h * 64 + cc * 16),
                 src + (size_t)row * ld + c * 32 + cc * 8);
        }
    };

    load_stage(0, 0);
    cp_commit();

    const int arow0 = warp_m * 64 + (lane >> 2);
    const int bcol0 = warp_n * 32 + (lane >> 2);

    for (int c = 0; c < nch; c++) {
        if (c + 1 < nch) {
            load_stage((c + 1) & 1, c + 1);
            cp_commit();
            cp_wait<1>();
        } else {
            cp_wait<0>();
        }
        __syncthreads();

        const char* stg = smc + (size_t)(c & 1) * STAGEB;
        const char* Ab  = stg;
        const char* Bb  = stg + TILEB;

#pragma unroll
        for (int b = 0; b < 2; b++) {
            const int kb = b * 32 + 8 * q;
            float2 Ah0[IT], Ah1[IT];
#pragma unroll
            for (int i = 0; i < IT; i++) {
                const int row = arow0 + i * 16;
                Ah0[i] = *reinterpret_cast<const float2*>(Ab + row * ROWB + kb);
                Ah1[i] = *reinterpret_cast<const float2*>(Ab + (row + 8) * ROWB + kb);
            }
            float2 Bh[WN];
#pragma unroll
            for (int j = 0; j < WN; j++)
                Bh[j] = *reinterpret_cast<const float2*>(
                    Bb + (bcol0 + j * 8) * ROWB + kb);
#pragma unroll
            for (int i = 0; i < IT; i++)
#pragma unroll
                for (int j = 0; j < WN; j++)
                    mma16(acc[i][j], f2u(Ah0[i].x), f2u(Ah1[i].x),
                          f2u(Ah0[i].y), f2u(Ah1[i].y), f2u(Bh[j].x), f2u(Bh[j].y));
            float2 Bl[WN];
#pragma unroll
            for (int j = 0; j < WN; j++)
                Bl[j] = *reinterpret_cast<const float2*>(
                    Bb + (bcol0 + j * 8) * ROWB + 64 + kb);
#pragma unroll
            for (int i = 0; i < IT; i++)
#pragma unroll
                for (int j = 0; j < WN; j++)
                    mma16(acc[i][j], f2u(Ah0[i].x), f2u(Ah1[i].x),
                          f2u(Ah0[i].y), f2u(Ah1[i].y), f2u(Bl[j].x), f2u(Bl[j].y));
            float2 Al0[IT], Al1[IT];
#pragma unroll
            for (int i = 0; i < IT; i++) {
                const int row = arow0 + i * 16;
                Al0[i] = *reinterpret_cast<const float2*>(Ab + row * ROWB + 64 + kb);
                Al1[i] = *reinterpret_cast<const float2*>(Ab + (row + 8) * ROWB + 64 + kb);
            }
#pragma unroll
            for (int i = 0; i < IT; i++)
#pragma unroll
                for (int j = 0; j < WN; j++)
                    mma16(acc[i][j], f2u(Al0[i].x), f2u(Al1[i].x),
                          f2u(Al0[i].y), f2u(Al1[i].y), f2u(Bh[j].x), f2u(Bh[j].y));
        }
        __syncthreads();
    }

    // ---------------- staged epilogues ----------------
    if (EPI == 0) {
        __nv_bfloat16* sh = reinterpret_cast<__nv_bfloat16*>(smc);
        __nv_bfloat16* sl = sh + 128 * 128;
#pragma unroll
        for (int i = 0; i < IT; i++) {
#pragma unroll
            for (int j = 0; j < WN; j++) {
                const float* a4 = acc[i][j];
                const int lr = warp_m * 64 + i * 16 + (lane >> 2);
                const int lc = warp_n * 32 + j * 8 + 2 * q;
                const float bx = bias_z[n0 + lc], by = bias_z[n0 + lc + 1];
                const int p0 = permkb(lc), p1 = permkb(lc + 1);
                const float v[4] = {a4[0] + bx, a4[1] + by, a4[2] + bx, a4[3] + by};
                const int rr[4] = {lr, lr, lr + 8, lr + 8};
                const int pp[4] = {p0, p1, p0, p1};
#pragma unroll
                for (int u = 0; u < 4; u++) {
                    const __nv_bfloat16 h = __float2bfloat16(v[u]);
                    sh[rr[u] * 128 + pp[u]] = h;
                    sl[rr[u] * 128 + pp[u]] =
                        __float2bfloat16(v[u] - __bfloat162float(h));
                }
            }
        }
        __syncthreads();
        __nv_bfloat16* Cz  = (__nv_bfloat16*)Cp  + (size_t)z * sC;
        __nv_bfloat16* C2z = (__nv_bfloat16*)C2p + (size_t)z * sC;
#pragma unroll
        for (int t = 0; t < 8; t++) {
            const int idx = tid + t * 256;
            const int row = idx >> 4;
            const int c16 = idx & 15;
            *reinterpret_cast<uint4*>(Cz + (size_t)(m0 + row) * ldc + n0 + c16 * 8) =
                *reinterpret_cast<const uint4*>(sh + row * 128 + c16 * 8);
            *reinterpret_cast<uint4*>(C2z + (size_t)(m0 + row) * ldc + n0 + c16 * 8) =
                *reinterpret_cast<const uint4*>(sl + row * 128 + c16 * 8);
        }
    } else {
        float* ss = reinterpret_cast<float*>(smc);
#pragma unroll
        for (int i = 0; i < IT; i++) {
#pragma unroll
            for (int j = 0; j < WN; j++) {
                const float* a4 = acc[i][j];
                const int lr = warp_m * 64 + i * 16 + (lane >> 2);
                const int lc = warp_n * 32 + j * 8 + 2 * q;
                const int p0 = permkb(lc), p1 = permkb(lc + 1);
                ss[lr * 128 + p0]       = alpha * a4[0];
                ss[lr * 128 + p1]       = alpha * a4[1];
                ss[(lr + 8) * 128 + p0] = alpha * a4[2];
                ss[(lr + 8) * 128 + p1] = alpha * a4[3];
            }
        }
        __syncthreads();
        float* Cz = (float*)Cp + (size_t)z * sC;
#pragma unroll
        for (int t = 0; t < 16; t++) {
            const int idx = tid + t * 256;
            const int row = idx >> 5;
            const int c8  = idx & 31;
            *reinterpret_cast<uint4*>(Cz + (size_t)(m0 + row) * ldc + n0 + c8 * 4) =
                *reinterpret_cast<const uint4*>(ss + row * 128 + c8 * 4);
        }
    }
}

// ===========================================================================
// fp16 single-pass GEMM (final): out = P @ VW + bvo[n] + query[m,n].
// ===========================================================================
__global__ void __launch_bounds__(256, 2) gemm_f16(
    const __half* __restrict__ A, const __half* __restrict__ B,
    float* __restrict__ C,
    const float* __restrict__ bias, const float* __restrict__ resid,
    int K, int lda, int ldb, int ldc,
    size_t sA, size_t sB, size_t sC)
{
    constexpr int IT = 4;
    constexpr int ROWB  = 80;
    constexpr int TILEB = 128 * ROWB;
    constexpr int STAGEB = 2 * TILEB;

    extern __shared__ char smc[];
    const uint32_t sb = smem_u32(smc);

    const int tid    = threadIdx.x;
    const int lane   = tid & 31;
    const int wid    = tid >> 5;
    const int warp_m = wid >> 2;
    const int warp_n = wid & 3;
    const int q      = lane & 3;
    const int n0 = blockIdx.x * 128;
    const int m0 = blockIdx.y * 128;
    const int z  = blockIdx.z;

    const __half* A0 = A + (size_t)z * sA + (size_t)m0 * lda;
    const __half* B0 = B + (size_t)z * sB + (size_t)n0 * ldb;

    float acc[IT][4][4];
#pragma unroll
    for (int i = 0; i < IT; i++)
#pragma unroll
        for (int j = 0; j < 4; j++)
#pragma unroll
            for (int l = 0; l < 4; l++) acc[i][j][l] = 0.0f;

    const int nch = K / 32;

    auto load_stage = [&](int buf, int c) {
        const uint32_t st = sb + (uint32_t)buf * STAGEB;
#pragma unroll
        for (int i = 0; i < 4; i++) {
            const int idx = tid + i * 256;
            const int tile = idx >> 9;
            const int w    = idx & 511;
            const int row  = w >> 2;
            const int cc   = w & 3;
            const __half* src = tile ? B0 : A0;
            const int ld = tile ? ldb : lda;
            cp16(st + (uint32_t)(tile * TILEB + row * ROWB + cc * 16),
                 src + (size_t)row * ld + c * 32 + cc * 8);
        }
    };

    load_stage(0, 0);
    cp_commit();

    const int arow0 = warp_m * 64 + (lane >> 2);
    const int bcol0 = warp_n * 32 + (lane >> 2);

    for (int c = 0; c < nch; c++) {
        if (c + 1 < nch) {
            load_stage((c + 1) & 1, c + 1);
            cp_commit();
            cp_wait<1>();
        } else {
            cp_wait<0>();
        }
        __syncthreads();

        const char* stg = smc + (size_t)(c & 1) * STAGEB;
        const char* Ab  = stg;
        const char* Bb  = stg + TILEB;

#pragma unroll
        for (int b = 0; b < 2; b++) {
            const int kb = b * 32 + 8 * q;
            float2 a0[IT], a1[IT], b0[4];
#pragma unroll
            for (int i = 0; i < IT; i++) {
                const int row = arow0 + i * 16;
                a0[i] = *reinterpret_cast<const float2*>(Ab + row * ROWB + kb);
                a1[i] = *reinterpret_cast<const float2*>(Ab + (row + 8) * ROWB + kb);
            }
#pragma unroll
            for (int j = 0; j < 4; j++)
                b0[j] = *reinterpret_cast<const float2*>(
                    Bb + (bcol0 + j * 8) * ROWB + kb);
#pragma unroll
            for (int i = 0; i < IT; i++)
#pragma unroll
                for (int j = 0; j < 4; j++)
                    mma16h(acc[i][j], f2u(a0[i].x), f2u(a1[i].x),
                           f2u(a0[i].y), f2u(a1[i].y), f2u(b0[j].x), f2u(b0[j].y));
        }
        __syncthreads();
    }

    float* Cz = C + (size_t)z * sC;
    const float* Rz = resid + (size_t)z * sC;
#pragma unroll
    for (int i = 0; i < IT; i++) {
#pragma unroll
        for (int j = 0; j < 4; j++) {
            const float* a4 = acc[i][j];
            const int r0 = m0 + warp_m * 64 + i * 16 + (lane >> 2);
            const int c0 = n0 + warp_n * 32 + j * 8 + 2 * q;
            const float bx = bias[c0], by = bias[c0 + 1];
            const float2 rs0 = *reinterpret_cast<const float2*>(
                &Rz[(size_t)r0 * ldc + c0]);
            const float2 rs1 = *reinterpret_cast<const float2*>(
                &Rz[(size_t)(r0 + 8) * ldc + c0]);
            float2 v0, v1;
            v0.x = a4[0] + bx + rs0.x; v0.y = a4[1] + by + rs0.y;
            v1.x = a4[2] + bx + rs1.x; v1.y = a4[3] + by + rs1.y;
            *reinterpret_cast<float2*>(&Cz[(size_t)r0 * ldc + c0]) = v0;
            *reinterpret_cast<float2*>(&Cz[(size_t)(r0 + 8) * ldc + c0]) = v1;
        }
    }
}

// ===========================================================================
// tf32 1-pass GEMM (VW^T): CTA 128x128, 256 thr occ 2, warp 64x32, K-chunk 32.
// Transposed fp16 output (permkb seq).
// ===========================================================================
constexpr int LDW    = 40;
constexpr int TILE_F = 128 * LDW;
constexpr int TILE_B = TILE_F * 4;

__device__ __forceinline__ void load_tile32(
    uint32_t sbase, const float* __restrict__ g, int ld, int tid)
{
#pragma unroll
    for (int i = 0; i < 4; i++) {
        const int f  = tid + i * 256;
        const int r  = f >> 3;
        const int c4 = (f & 7) << 2;
        cp16(sbase + (uint32_t)(r * LDW + c4) * 4, g + (size_t)r * ld + c4);
    }
}

__global__ void __launch_bounds__(256, 2) gemm_t32_vw(
    const float* __restrict__ A, const float* __restrict__ B,
    __half* __restrict__ C, int K, int lda, int ldb)
{
    constexpr int IT = 4;
    extern __shared__ float smf[];
    const uint32_t sb = smem_u32(smf);

    const int tid    = threadIdx.x;
    const int lane   = tid & 31;
    const int wid    = tid >> 5;
    const int warp_m = wid >> 2;
    const int warp_n = wid & 3;
    const int n0 = blockIdx.x * 128;
    const int m0 = blockIdx.y * 128;

    const float* A0 = A + (size_t)m0 * lda;
    const float* B0 = B + (size_t)n0 * ldb;

    float acc[IT][4][4];
#pragma unroll
    for (int i = 0; i < IT; i++)
#pragma unroll
        for (int j = 0; j < 4; j++)
#pragma unroll
            for (int l = 0; l < 4; l++) acc[i][j][l] = 0.0f;

    const int nch = K / 32;

    auto load_stage = [&](int buf, int c) {
        const uint32_t st = sb + (uint32_t)buf * 2 * TILE_B;
        load_tile32(st,          A0 + c * 32, lda, tid);
        load_tile32(st + TILE_B, B0 + c * 32, ldb, tid);
    };

    load_stage(0, 0);
    cp_commit();

    const int arow0 = warp_m * 64 + (lane >> 2);
    const int bcol0 = warp_n * 32 + (lane >> 2);
    const int kq2   = 2 * (lane & 3);

    for (int c = 0; c < nch; c++) {
        if (c + 1 < nch) {
            load_stage((c + 1) & 1, c + 1);
            cp_commit();
            cp_wait<1>();
        } else {
            cp_wait<0>();
        }
        __syncthreads();

        const float* st  = smf + (size_t)(c & 1) * 2 * TILE_F;
        const float* Ath = st;
        const float* Bth = st + TILE_F;

#pragma unroll
        for (int s = 0; s < 4; s++) {
            const int ko = s * 8 + kq2;
            float2 a0[IT], a1[IT], b0[4];
#pragma unroll
            for (int i = 0; i < IT; i++) {
                a0[i] = *reinterpret_cast<const float2*>(
                    Ath + (size_t)(arow0 + i * 16) * LDW + ko);
                a1[i] = *reinterpret_cast<const float2*>(
                    Ath + (size_t)(arow0 + i * 16 + 8) * LDW + ko);
            }
#pragma unroll
            for (int j = 0; j < 4; j++)
                b0[j] = *reinterpret_cast<const float2*>(
                    Bth + (size_t)(bcol0 + j * 8) * LDW + ko);
#pragma unroll
            for (int i = 0; i < IT; i++)
#pragma unroll
                for (int j = 0; j < 4; j++)
                    mma8(acc[i][j], a0[i].x, a1[i].x, a0[i].y, a1[i].y,
                         b0[j].x, b0[j].y);
        }
        __syncthreads();
    }

#pragma unroll
    for (int i = 0; i < IT; i++) {
#pragma unroll
        for (int j = 0; j < 4; j++) {
            const float* a4 = acc[i][j];
            const int r0 = m0 + warp_m * 64 + i * 16 + (lane >> 2);
            const int c0 = n0 + warp_n * 32 + j * 8 + 2 * (lane & 3);
            const int b0i = r0 >> 11,        sx0 = permkb(r0 & (SEQ - 1));
            const int b1i = (r0 + 8) >> 11,  sx1 = permkb((r0 + 8) & (SEQ - 1));
            __half* p0 = C + (size_t)b0i * DIM * SEQ;
            __half* p1 = C + (size_t)b1i * DIM * SEQ;
            p0[(size_t)c0 * SEQ + sx0]       = __float2half(a4[0]);
            p0[(size_t)(c0 + 1) * SEQ + sx0] = __float2half(a4[1]);
            p1[(size_t)c0 * SEQ + sx1]       = __float2half(a4[2]);
            p1[(size_t)(c0 + 1) * SEQ + sx1] = __float2half(a4[3]);
        }
    }
}

// ===========================================================================
// Wvo GEMM: 64x64 CTA tile (grid 8x8), 256 thr, warp 32x16, K=512, tf32.
// Writes Wvo^T[n*DIM + permk(m)].
// ===========================================================================
__global__ void __launch_bounds__(256, 2) gemm_wvo(
    const float* __restrict__ A, const float* __restrict__ B,
    float* __restrict__ C)
{
    constexpr int T64F = 64 * LDW;
    constexpr int T64B = T64F * 4;
    extern __shared__ float smf[];
    const uint32_t sb = smem_u32(smf);

    const int tid    = threadIdx.x;
    const int lane   = tid & 31;
    const int wid    = tid >> 5;
    const int warp_m = wid >> 2;
    const int warp_n = wid & 3;
    const int n0 = blockIdx.x * 64;
    const int m0 = blockIdx.y * 64;

    const float* A0 = A + (size_t)m0 * DIM;
    const float* B0 = B + (size_t)n0 * DIM;

    float acc[2][2][4];
#pragma unroll
    for (int i = 0; i < 2; i++)
#pragma unroll
        for (int j = 0; j < 2; j++)
#pragma unroll
            for (int l = 0; l < 4; l++) acc[i][j][l] = 0.0f;

    auto load_stage = [&](int buf, int c) {
        const uint32_t st = sb + (uint32_t)buf * 2 * T64B;
#pragma unroll
        for (int i = 0; i < 4; i++) {
            const int f = tid + i * 256;
            const int tile = f >> 9;
            const int w = f & 511;
            const int r  = w >> 3;
            const int c4 = (w & 7) << 2;
            const float* src = tile ? B0 : A0;
            cp16(st + (uint32_t)(tile * T64B) + (uint32_t)(r * LDW + c4) * 4,
                 src + (size_t)r * DIM + c * 32 + c4);
        }
    };

    load_stage(0, 0);
    cp_commit();

    const int arow0 = warp_m * 32 + (lane >> 2);
    const int bcol0 = warp_n * 16 + (lane >> 2);
    const int kq2   = 2 * (lane & 3);

    for (int c = 0; c < 16; c++) {
        if (c + 1 < 16) {
            load_stage((c + 1) & 1, c + 1);
            cp_commit();
            cp_wait<1>();
        } else {
            cp_wait<0>();
        }
        __syncthreads();

        const float* st  = smf + (size_t)(c & 1) * 2 * T64F;
        const float* Ath = st;
        const float* Bth = st + T64F;

#pragma unroll
        for (int s = 0; s < 4; s++) {
            const int ko = s * 8 + kq2;
            float2 a0[2], a1[2], b0[2];
#pragma unroll
            for (int i = 0; i < 2; i++) {
                a0[i] = *reinterpret_cast<const float2*>(
                    Ath + (size_t)(arow0 + i * 16) * LDW + ko);
                a1[i] = *reinterpret_cast<const float2*>(
                    Ath + (size_t)(arow0 + i * 16 + 8) * LDW + ko);
            }
#pragma unroll
            for (int j = 0; j < 2; j++)
                b0[j] = *reinterpret_cast<const float2*>(
                    Bth + (size_t)(bcol0 + j * 8) * LDW + ko);
#pragma unroll
            for (int i = 0; i < 2; i++)
#pragma unroll
                for (int j = 0; j < 2; j++)
                    mma8(acc[i][j], a0[i].x, a1[i].x, a0[i].y, a1[i].y,
                         b0[j].x, b0[j].y);
        }
        __syncthreads();
    }

#pragma unroll
    for (int i = 0; i < 2; i++) {
#pragma unroll
        for (int j = 0; j < 2; j++) {
            const float* a4 = acc[i][j];
            const int r0 = m0 + warp_m * 32 + i * 16 + (lane >> 2);
            const int c0 = n0 + warp_n * 16 + j * 8 + 2 * (lane & 3);
            const int pr0 = permk(r0), pr1 = permk(r0 + 8);
            C[(size_t)c0 * DIM + pr0]       = tf32_rna(a4[0]);
            C[(size_t)(c0 + 1) * DIM + pr0] = tf32_rna(a4[1]);
            C[(size_t)c0 * DIM + pr1]       = tf32_rna(a4[2]);
            C[(size_t)(c0 + 1) * DIM + pr1] = tf32_rna(a4[3]);
        }
    }
}

// ---------------- prep kernels ----------------------------------------------
// Chain A: bf16 splits of query + key_value (no kv32 here).
__global__ void split_all(const float4* __restrict__ q, const float4* __restrict__ kv,
                          __nv_bfloat16* __restrict__ dh,
                          __nv_bfloat16* __restrict__ dl, int n4)
{
    int id = blockIdx.x * 256 + threadIdx.x;
    if (id >= 2 * n4) return;
    const float4 v = (id >= n4) ? kv[id - n4] : q[id];
    const int e0 = id * 4;
    const int base = e0 & ~511;
    const float vv[4] = {v.x, v.y, v.z, v.w};
#pragma unroll
    for (int u = 0; u < 4; u++) {
        const int k = (e0 + u) & 511;
        const float x = vv[u];
        const __nv_bfloat16 h = __float2bfloat16(x);
        const int pb = permkb(k);
        dh[base + pb] = h;
        dl[base + pb] = __float2bfloat16(x - __bfloat162float(h));
    }
}

// Chain B: kv -> tf32 permk layout.
__global__ void kv32_prep(const float4* __restrict__ kv, float* __restrict__ kv32,
                          int n4)
{
    const int id = blockIdx.x * 256 + threadIdx.x;
    if (id >= n4) return;
    const float4 v = kv[id];
    const int e0 = id * 4;
    const int base = e0 & ~511;
    const float vv[4] = {v.x, v.y, v.z, v.w};
#pragma unroll
    for (int u = 0; u < 4; u++) {
        const int k = (e0 + u) & 511;
        kv32[base + permk(k)] = tf32_rna(vv[u]);
    }
}

// Chain A: Wq, Wk bf16 split transposed (permkb).
__global__ void wprep_qk(const float* __restrict__ Wq, const float* __restrict__ Wk,
                         __nv_bfloat16* __restrict__ wbh,
                         __nv_bfloat16* __restrict__ wbl)
{
    const int idx = blockIdx.x * 256 + threadIdx.x;
    const int wsel = blockIdx.y;
    const int n = idx & 511;
    const int k = idx >> 9;
    const float w = (wsel ? Wk : Wq)[(size_t)k * DIM + n];
    const __nv_bfloat16 h = __float2bfloat16(w);
    const size_t dst = (size_t)wsel * DIM * DIM + (size_t)n * DIM + permkb(k);
    wbh[dst] = h;
    wbl[dst] = __float2bfloat16(w - __bfloat162float(h));
}

// Chain B: Wv non-transposed (perm cols), Wo transposed (perm cols).
__global__ void wprep_vo(const float* __restrict__ Wv, const float* __restrict__ Wo,
                         float* __restrict__ wvnt, float* __restrict__ wot)
{
    const int idx = blockIdx.x * 256 + threadIdx.x;
    const int wsel = blockIdx.y;
    const int n = idx & 511;
    const int k = idx >> 9;
    if (wsel == 0) {
        const float w = Wv[(size_t)k * DIM + n];
        wvnt[(size_t)k * DIM + permk(n)] = tf32_rna(w);
    } else {
        const float w = Wo[(size_t)k * DIM + n];
        wot[(size_t)n * DIM + permk(k)] = tf32_rna(w);
    }
}

__global__ void bvo_kernel(const float* __restrict__ bv, const float* __restrict__ Wo,
                           const float* __restrict__ bo, float* __restrict__ bvo)
{
    __shared__ float red[256];
    const int tid = threadIdx.x;
    const int n = blockIdx.x * 64 + (tid & 63);
    const int part = tid >> 6;
    float s = 0.0f;
    for (int j = part * 128; j < part * 128 + 128; j++)
        s += bv[j] * Wo[(size_t)j * DIM + n];
    red[tid] = s;
    __syncthreads();
    if (tid < 64)
        bvo[n] = bo[n] + red[tid] + red[tid + 64] + red[tid + 128] + red[tid + 192];
}

__global__ void __launch_bounds__(256) softmax_rows(const float* __restrict__ S,
                                                    __half* __restrict__ P)
{
    const size_t row = blockIdx.x;
    const float4* p4 = reinterpret_cast<const float4*>(S + row * (size_t)SEQ);
    __half2* po2 = reinterpret_cast<__half2*>(P + row * (size_t)SEQ);
    const int t = threadIdx.x;
    const int lane = t & 31;
    const int wid  = t >> 5;

    float4 v0 = p4[t];
    float4 v1 = p4[t + 256];
    float m = fmaxf(fmaxf(fmaxf(v0.x, v0.y), fmaxf(v0.z, v0.w)),
                    fmaxf(fmaxf(v1.x, v1.y), fmaxf(v1.z, v1.w)));
#pragma unroll
    for (int o = 16; o > 0; o >>= 1)
        m = fmaxf(m, __shfl_xor_sync(0xFFFFFFFFu, m, o));
    __shared__ float wred[8];
    if (lane == 0) wred[wid] = m;
    __syncthreads();
    m = wred[0];
#pragma unroll
    for (int w = 1; w < 8; w++) m = fmaxf(m, wred[w]);

    v0.x = __expf(v0.x - m); v0.y = __expf(v0.y - m);
    v0.z = __expf(v0.z - m); v0.w = __expf(v0.w - m);
    v1.x = __expf(v1.x - m); v1.y = __expf(v1.y - m);
    v1.z = __expf(v1.z - m); v1.w = __expf(v1.w - m);
    float sum = (v0.x + v0.y) + (v0.z + v0.w) + (v1.x + v1.y) + (v1.z + v1.w);
#pragma unroll
    for (int o = 16; o > 0; o >>= 1)
        sum += __shfl_xor_sync(0xFFFFFFFFu, sum, o);
    __shared__ float wsum[8];
    if (lane == 0) wsum[wid] = sum;
    __syncthreads();
    sum = wsum[0];
#pragma unroll
    for (int w = 1; w < 8; w++) sum += wsum[w];
    const float inv = 1.0f / sum;

    po2[2 * t + 0]   = __floats2half2_rn(v0.x * inv, v0.y * inv);
    po2[2 * t + 1]   = __floats2half2_rn(v0.z * inv, v0.w * inv);
    po2[2 * (t + 256) + 0] = __floats2half2_rn(v1.x * inv, v1.y * inv);
    po2[2 * (t + 256) + 1] = __floats2half2_rn(v1.z * inv, v1.w * inv);
}

// ---------------- launcher --------------------------------------------------
extern "C" void kernel_launch(void* const* d_in, const int* in_sizes, int n_in,
                              void* d_out, int out_size)
{
    (void)in_sizes; (void)n_in; (void)out_size;
    const float* query     = (const float*)d_in[0];
    const float* key_value = (const float*)d_in[1];
    const float* Wq = (const float*)d_in[2];
    const float* bq = (const float*)d_in[3];
    const float* Wk = (const float*)d_in[4];
    const float* bk = (const float*)d_in[5];
    const float* Wv = (const float*)d_in[6];
    const float* bv = (const float*)d_in[7];
    const float* Wo = (const float*)d_in[8];
    const float* bo = (const float*)d_in[9];
    float* out = (float*)d_out;

    __nv_bfloat16 *in_bh, *in_bl, *qk_bh, *qk_bl, *wbh, *wbl;
    __half *vwt, *pf;
    float *kv_t32, *s, *wvnt, *wot, *wvot, *bvo;
    cudaGetSymbolAddress((void**)&in_bh,  g_in_bh);
    cudaGetSymbolAddress((void**)&in_bl,  g_in_bl);
    cudaGetSymbolAddress((void**)&kv_t32, g_kv_t32);
    cudaGetSymbolAddress((void**)&qk_bh,  g_qk_bh);
    cudaGetSymbolAddress((void**)&qk_bl,  g_qk_bl);
    cudaGetSymbolAddress((void**)&vwt,    g_vwt);
    cudaGetSymbolAddress((void**)&s,      g_s);
    cudaGetSymbolAddress((void**)&pf,     g_pf);
    cudaGetSymbolAddress((void**)&wbh,    g_wqk_bh);
    cudaGetSymbolAddress((void**)&wbl,    g_wqk_bl);
    cudaGetSymbolAddress((void**)&wvnt,   g_wvnt);
    cudaGetSymbolAddress((void**)&wot,    g_wot);
    cudaGetSymbolAddress((void**)&wvot,   g_wvot);
    cudaGetSymbolAddress((void**)&bvo,    g_bvo);

    constexpr int SMB = 2 * 2 * 128 * 160;    // 81920 B
    constexpr int SMH = 2 * 2 * 128 * 80;     // 40960 B
    constexpr int SM1 = 2 * 2 * TILE_B;       // 81920 B
    constexpr int SMW = 2 * 2 * 64 * LDW * 4; // 40960 B
    cudaFuncSetAttribute(gemm_bf16<0>, cudaFuncAttributeMaxDynamicSharedMemorySize, SMB);
    cudaFuncSetAttribute(gemm_bf16<2>, cudaFuncAttributeMaxDynamicSharedMemorySize, SMB);
    cudaFuncSetAttribute(gemm_f16, cudaFuncAttributeMaxDynamicSharedMemorySize, SMH);
    cudaFuncSetAttribute(gemm_t32_vw, cudaFuncAttributeMaxDynamicSharedMemorySize, SM1);
    cudaFuncSetAttribute(gemm_wvo, cudaFuncAttributeMaxDynamicSharedMemorySize, SMW);

    // ---- second stream + fork/join events (created once; host-side only)
    static cudaStream_t s2 = nullptr;
    static cudaEvent_t evF = nullptr, evJ = nullptr;
    if (s2 == nullptr) {
        cudaStreamCreateWithFlags(&s2, cudaStreamNonBlocking);
        cudaEventCreateWithFlags(&evF, cudaEventDisableTiming);
        cudaEventCreateWithFlags(&evJ, cudaEventDisableTiming);
    }

    const size_t sQKV = (size_t)SEQ * DIM;
    const size_t sS   = (size_t)SEQ * SEQ;
    const size_t sVT  = (size_t)DIM * SEQ;
    const int n4 = (int)(BND / 4);

    // fork s2 from the main stream
    cudaEventRecord(evF, 0);
    cudaStreamWaitEvent(s2, evF, 0);

    // ===== chain B (stream s2): kv32 -> wprep_vo -> Wvo -> bvo -> VW =====
    kv32_prep<<<n4 / 256, 256, 0, s2>>>((const float4*)key_value, kv_t32, n4);
    {
        dim3 g((DIM * DIM) / 256, 2);
        wprep_vo<<<g, 256, 0, s2>>>(Wv, Wo, wvnt, wot);
    }
    gemm_wvo<<<dim3(8, 8), 256, SMW, s2>>>(wvnt, wot, wvot);
    bvo_kernel<<<DIM / 64, 256, 0, s2>>>(bv, Wo, bo, bvo);
    {
        dim3 grid(DIM / 128, (BB * SEQ) / 128, 1);
        gemm_t32_vw<<<grid, 256, SM1, s2>>>(kv_t32, wvot, vwt, DIM, DIM, DIM);
    }
    cudaEventRecord(evJ, s2);

    // ===== chain A (main stream): splits -> proj -> QK^T -> softmax =====
    split_all<<<(2 * n4) / 256, 256>>>((const float4*)query,
        (const float4*)key_value, in_bh, in_bl, n4);
    {
        dim3 g((DIM * DIM) / 256, 2);
        wprep_qk<<<g, 256>>>(Wq, Wk, wbh, wbl);
    }
    {
        dim3 grid(DIM / 128, (BB * SEQ) / 128, 2);
        gemm_bf16<0><<<grid, 256, SMB>>>(in_bh, in_bl, wbh, wbl,
            qk_bh, qk_bl, bq, bk, DIM, DIM, DIM, DIM,
            BND, (size_t)DIM * DIM, BND, 1.0f);
    }
    {
        dim3 grid(SEQ / 128, SEQ / 128, BB);
        gemm_bf16<2><<<grid, 256, SMB>>>(qk_bh, qk_bl, qk_bh + BND, qk_bl + BND,
            s, nullptr, nullptr, nullptr, DIM, DIM, DIM, SEQ,
            sQKV, sQKV, sS, SCALE_F);
    }
    softmax_rows<<<BB * SEQ, 256>>>(s, pf);

    // join: final kernel needs pf (chain A) and vwt/bvo (chain B)
    cudaStreamWaitEvent(0, evJ, 0);
    {
        dim3 grid(DIM / 128, SEQ / 128, BB);
        gemm_f16<<<grid, 256, SMH>>>(pf, vwt, out, bvo, query,
                                     SEQ, SEQ, SEQ, DIM, sS, sVT, sQKV);
    }
}